// round 11
// baseline (speedup 1.0000x reference)
#include <cuda_runtime.h>
#include <cuda_fp16.h>
#include <math.h>

// ---------------- problem constants ----------------
#define Bb 4
#define Ll 2048
#define Dd 2048
#define NHh 16
#define DHh 128
#define DHRr 64
#define DCc 1024
#define Mtok (Bb*Ll)            // 8192
#define QKD 192                 // DH + DHR
#define N1 (DCc + DCc + DHRr)   // 2112 : [ckv | cq | kr]
#define N2 (Dd + Dd)            // 4096 : [kc | vfl]
#define N3 (Dd + NHh*DHRr)      // 3072 : [qc | qr]

// ---------------- device scratch (static, allocation-free) ----------------
__device__ __half g_xh  [(size_t)Mtok*Dd];
__device__ __half g_w1t [(size_t)N1*Dd];
__device__ __half g_w2t [(size_t)N2*DCc];
__device__ __half g_w3t [(size_t)N3*DCc];
__device__ __half g_woT [(size_t)Dd*Dd];
__device__ __half g_c1  [(size_t)Mtok*N1];   // ckv | cq | kr
__device__ __half g_c2  [(size_t)Mtok*N2];   // kc | vfl
__device__ __half g_c3  [(size_t)Mtok*N3];   // qc | qr
__device__ __half g_q   [(size_t)Bb*NHh*Ll*QKD];
__device__ __half g_k   [(size_t)Bb*NHh*Ll*QKD];
__device__ __half g_vt  [(size_t)Bb*NHh*DHh*Ll];   // [bh][d][l]
__device__ __half g_ao  [(size_t)Mtok*Dd];
__device__ float  g_cs  [Ll*32];
__device__ float  g_sn  [Ll*32];

// ---------------- asm helpers ----------------
__device__ __forceinline__ void mma_h16(float* d, const unsigned* a, const unsigned* b) {
    asm volatile(
        "mma.sync.aligned.m16n8k16.row.col.f32.f16.f16.f32 "
        "{%0,%1,%2,%3}, {%4,%5,%6,%7}, {%8,%9}, {%0,%1,%2,%3};"
        : "+f"(d[0]), "+f"(d[1]), "+f"(d[2]), "+f"(d[3])
        : "r"(a[0]), "r"(a[1]), "r"(a[2]), "r"(a[3]), "r"(b[0]), "r"(b[1]));
}

__device__ __forceinline__ unsigned smem_u32(const void* p) {
    return (unsigned)__cvta_generic_to_shared(p);
}

__device__ __forceinline__ void ldsm4(unsigned* r, unsigned addr) {
    asm volatile("ldmatrix.sync.aligned.m8n8.x4.shared.b16 {%0,%1,%2,%3}, [%4];"
        : "=r"(r[0]), "=r"(r[1]), "=r"(r[2]), "=r"(r[3]) : "r"(addr));
}

__device__ __forceinline__ void cp16(unsigned dst, const void* src) {
    asm volatile("cp.async.cg.shared.global [%0], [%1], 16;" :: "r"(dst), "l"(src));
}
#define CP_COMMIT() asm volatile("cp.async.commit_group;")
#define CP_WAIT(N)  asm volatile("cp.async.wait_group %0;" :: "n"(N))

// ---------------- fused pre-pass: rope table + x->fp16 + 8 weight transposes
// block regions: [0,256) rope; [256,16640) cvt_x; rest: 32x32 wtrans tiles
#define PRE_ROPE 256
#define PRE_CVT  16384
#define PRE_NBLK (PRE_ROPE + PRE_CVT + 2048*5 + 128 + 1024 + 4096)   // 32128
__global__ void __launch_bounds__(256) fused_pre(
    const float* __restrict__ x,
    const float* __restrict__ WDKV, const float* __restrict__ WDQ,
    const float* __restrict__ WKR,  const float* __restrict__ WUK,
    const float* __restrict__ WUV,  const float* __restrict__ WUQ,
    const float* __restrict__ WQR,  const float* __restrict__ WO)
{
    __shared__ __half tsh[32][33];
    int bid = blockIdx.x;
    const int tid = threadIdx.x;

    if (bid < PRE_ROPE) {                    // rope tables
        int idx = bid*256 + tid;
        int l = idx >> 5, jj = idx & 31;
        float inv = powf(10000.0f, -(float)jj/32.0f);
        float ang = (float)l * inv;
        g_cs[l*32 + jj] = cosf(ang);
        g_sn[l*32 + jj] = sinf(ang);
        return;
    }
    bid -= PRE_ROPE;
    if (bid < PRE_CVT) {                     // x fp32 -> fp16
        int i = bid*256 + tid;
        float4 v = ((const float4*)x)[i];
        __half2* o = (__half2*)g_xh;
        o[2*i]   = __floats2half2_rn(v.x, v.y);
        o[2*i+1] = __floats2half2_rn(v.z, v.w);
        return;
    }
    bid -= PRE_CVT;

    const float* W; __half* Wt; int K, N, t;
    if      (bid <  2048) { W=WDKV; Wt=g_w1t;                   K=Dd;  N=DCc;      t=bid; }
    else if (bid <  4096) { W=WDQ;  Wt=g_w1t+(size_t)DCc*Dd;    K=Dd;  N=DCc;      t=bid-2048; }
    else if (bid <  4224) { W=WKR;  Wt=g_w1t+(size_t)2*DCc*Dd;  K=Dd;  N=DHRr;     t=bid-4096; }
    else if (bid <  6272) { W=WUK;  Wt=g_w2t;                   K=DCc; N=Dd;       t=bid-4224; }
    else if (bid <  8320) { W=WUV;  Wt=g_w2t+(size_t)Dd*DCc;    K=DCc; N=Dd;       t=bid-6272; }
    else if (bid < 10368) { W=WUQ;  Wt=g_w3t;                   K=DCc; N=Dd;       t=bid-8320; }
    else if (bid < 11392) { W=WQR;  Wt=g_w3t+(size_t)Dd*DCc;    K=DCc; N=NHh*DHRr; t=bid-10368; }
    else                  { W=WO;   Wt=g_woT;                   K=Dd;  N=Dd;       t=bid-11392; }

    const int nx = N/32;
    const int n0 = (t % nx)*32, k0 = (t / nx)*32;
    const int tx = tid & 31, ty = tid >> 5;
#pragma unroll
    for (int i=0;i<4;i++)
        tsh[ty+i*8][tx] = __float2half(W[(size_t)(k0+ty+i*8)*N + n0+tx]);
    __syncthreads();
#pragma unroll
    for (int i=0;i<4;i++)
        Wt[(size_t)(n0+ty+i*8)*K + k0+tx] = tsh[tx][ty+i*8];
}

// ---------------- fp16 tensor-core GEMM: C[M][N] = A * Bt^T ----------------
// 128x128 CTA tile; K-stages of 64 halves; 3-stage cp.async ring; ldmatrix;
// 8 warps (2x4), 64x32 warp tile; 2 CTAs/SM.
#define SW 36
#define GST (128*SW)
template<bool OUTF32>
__global__ void __launch_bounds__(256, 2)
h16_gemm(const __half* __restrict__ A, const __half* __restrict__ Bt,
         void* __restrict__ Cv, int N, int K, int lda, int ldc)
{
    extern __shared__ unsigned gsm[];
    const unsigned sA = smem_u32(gsm);
    const unsigned sB = sA + 3*GST*4;

    const int tid  = threadIdx.x;
    const int lane = tid & 31;
    const int warp = tid >> 5;
    const int wm = warp >> 2, wn = warp & 3;
    const int ln15 = lane & 15;
    const int hi16 = (lane >> 4) * 16;

    const __half* Ag = A  + (size_t)blockIdx.y * 128 * lda;
    const __half* Bg = Bt + (size_t)blockIdx.x * 128 * K;
    const int nrem = N - blockIdx.x*128;

    unsigned afo[4], bfo[2];
#pragma unroll
    for (int ma=0; ma<4; ma++) afo[ma] = ((wm*64 + ma*16 + ln15)*SW)*4 + hi16;
#pragma unroll
    for (int nb=0; nb<2; nb++) bfo[nb] = ((wn*32 + nb*16 + ln15)*SW)*4 + hi16;

    float acc[4][4][4];
#pragma unroll
    for (int i=0;i<4;i++)
#pragma unroll
        for (int j=0;j<4;j++)
#pragma unroll
            for (int t=0;t<4;t++) acc[i][j][t]=0.f;

    const int nk = K/64;

    auto fill = [&](int s, int k0) {
        const unsigned aB = sA + s*GST*4;
        const unsigned bB = sB + s*GST*4;
#pragma unroll
        for (int i = 0; i < 4; i++) {
            int idx = tid + i*256;
            int row = idx >> 3, ch = idx & 7;
            cp16(aB + row*SW*4 + ch*16, Ag + (size_t)row*lda + k0 + ch*8);
        }
#pragma unroll
        for (int i = 0; i < 4; i++) {
            int idx = tid + i*256;
            int row = idx >> 3, ch = idx & 7;
            int gr = (row < nrem) ? row : (nrem-1);
            cp16(bB + row*SW*4 + ch*16, Bg + (size_t)gr*K + k0 + ch*8);
        }
    };

    fill(0, 0);  CP_COMMIT();
    fill(1, 64); CP_COMMIT();

    for (int kt=0; kt<nk; kt++) {
        CP_WAIT(1);
        __syncthreads();

        const int kn = kt+2;
        if (kn < nk) fill(kn % 3, kn*64);
        CP_COMMIT();

        const unsigned aS = sA + (kt%3)*GST*4;
        const unsigned bS = sB + (kt%3)*GST*4;
#pragma unroll
        for (int kc8 = 0; kc8 < 32; kc8 += 8) {
            unsigned af[4][4];
#pragma unroll
            for (int ma=0;ma<4;ma++)
                ldsm4(af[ma], aS + afo[ma] + kc8*4);
#pragma unroll
            for (int nb=0;nb<2;nb++) {
                unsigned bq[4];
                ldsm4(bq, bS + bfo[nb] + kc8*4);
                unsigned b0[2] = {bq[0], bq[2]};
                unsigned b1[2] = {bq[1], bq[3]};
#pragma unroll
                for (int ma=0;ma<4;ma++) {
                    mma_h16(acc[ma][nb*2  ], af[ma], b0);
                    mma_h16(acc[ma][nb*2+1], af[ma], b1);
                }
            }
        }
    }

    const int r = lane >> 2, c = lane & 3;
#pragma unroll
    for (int ma=0;ma<4;ma++) {
        int m = blockIdx.y*128 + wm*64 + ma*16 + r;
#pragma unroll
        for (int na=0;na<4;na++) {
            int n = blockIdx.x*128 + wn*32 + na*8 + 2*c;
            if (n < N) {
                if (OUTF32) {
                    float* C = (float*)Cv;
                    *(float2*)&C[(size_t)m*ldc + n]     = make_float2(acc[ma][na][0], acc[ma][na][1]);
                    *(float2*)&C[(size_t)(m+8)*ldc + n] = make_float2(acc[ma][na][2], acc[ma][na][3]);
                } else {
                    __half* C = (__half*)Cv;
                    *(__half2*)&C[(size_t)m*ldc + n]     = __floats2half2_rn(acc[ma][na][0], acc[ma][na][1]);
                    *(__half2*)&C[(size_t)(m+8)*ldc + n] = __floats2half2_rn(acc[ma][na][2], acc[ma][na][3]);
                }
            }
        }
    }
}

// ---------------- prep3: fused (RoPE+concat+normalize) and V-transpose -----
// blocks [0, Mtok*NHh): prep work (192 active threads of 256)
// blocks [Mtok*NHh, +2048): vtrans work
__global__ void __launch_bounds__(256) prep3(const float* __restrict__ s_qk_ptr)
{
    __shared__ float red[2][6];
    __shared__ __half tv[64][DHh+8];

    int bid = blockIdx.x;
    const int t = threadIdx.x;

    if (bid < Mtok*NHh) {
        const int bl = bid & (Mtok-1);
        const int h  = bid >> 13;          // Mtok = 2^13
        const int b = bl >> 11, l = bl & 2047;
        const float s_qk = *s_qk_ptr;

        float kv = 0.f, qv = 0.f;
        if (t < 128) {
            kv = __half2float(g_c2[(size_t)bl*N2 + h*DHh + t]);
            qv = __half2float(g_c3[(size_t)bl*N3 + h*DHh + t]);
        } else if (t < 192) {
            int j = t - 128, jj = j & 31;
            float csv = g_cs[l*32 + jj];
            float snv = g_sn[l*32 + jj];
            {
                const __half* krp = g_c1 + (size_t)bl*N1 + 2*DCc;
                float v  = __half2float(krp[j]);
                float vo = __half2float(krp[(j<32 ? j+32 : j-32)]);
                float rot = (j<32) ? -vo : vo;
                kv = v*csv + rot*snv;
            }
            {
                const __half* qrp = g_c3 + (size_t)bl*N3 + Dd + h*DHRr;
                float v  = __half2float(qrp[j]);
                float vo = __half2float(qrp[(j<32 ? j+32 : j-32)]);
                float rot = (j<32) ? -vo : vo;
                qv = v*csv + rot*snv;
            }
        }

        float ks = kv*kv, qs = qv*qv;
#pragma unroll
        for (int o=16;o>0;o>>=1) {
            ks += __shfl_xor_sync(0xffffffffu, ks, o);
            qs += __shfl_xor_sync(0xffffffffu, qs, o);
        }
        const int w = t >> 5;
        if ((t & 31) == 0 && w < 6) { red[0][w] = ks; red[1][w] = qs; }
        __syncthreads();
        if (t < 192) {
            float ksum = red[0][0]+red[0][1]+red[0][2]+red[0][3]+red[0][4]+red[0][5];
            float qsum = red[1][0]+red[1][1]+red[1][2]+red[1][3]+red[1][4]+red[1][5];
            float invk = 1.0f / fmaxf(sqrtf(ksum), 1e-12f);
            float invq = s_qk / fmaxf(sqrtf(qsum), 1e-12f);
            size_t off = ((size_t)(b*NHh + h)*Ll + l)*QKD + t;
            g_k[off] = __float2half(kv*invk);
            g_q[off] = __float2half(qv*invq);
        }
        return;
    }

    // ---- vtrans part ----
    const int vb = bid - Mtok*NHh;
    const int bh = vb >> 5, lxb = vb & 31;
    const int b = bh >> 4, h = bh & 15;
    const int l0 = lxb * 64;

    for (int i = t; i < 64*16; i += 256) {
        int l = i >> 4, ch = i & 15;
        *(uint4*)&tv[l][ch*8] =
            *(const uint4*)(g_c2 + ((size_t)(b*Ll + l0 + l))*N2 + Dd + h*DHh + ch*8);
    }
    __syncthreads();
    for (int i = t; i < 128*8; i += 256) {
        int d = i >> 3, ch = i & 7;
        __half2 p[4];
#pragma unroll
        for (int u=0;u<4;u++) {
            int l = ch*8 + u*2;
            p[u] = __halves2half2(tv[l][d], tv[l+1][d]);
        }
        *(uint4*)(g_vt + (size_t)bh*DHh*Ll + (size_t)d*Ll + l0 + ch*8) = *(uint4*)p;
    }
}

// ---------------- fp16 flash attention (causal, BQ=128, BK=64) -------------
// Q fragments in registers; 3-stage cp.async K/V ring -> ONE barrier per tile.
#define QS 100
#define VS 36
#define KST (64*QS)
#define VST (128*VS)
#define AST 3
__global__ void __launch_bounds__(256, 1) attn_h16()
{
    extern __shared__ unsigned smu[];
    unsigned* Qs = smu;
    const unsigned sQ = smem_u32(Qs);
    const unsigned sK = sQ + 128*QS*4;          // 3 stages [64][100]
    const unsigned sV = sK + AST*KST*4;         // 3 stages [128][36]
    const unsigned sP = sV + AST*VST*4;         // [128][36]
    unsigned* Ps = smu + (128*QS + AST*KST + AST*VST);

    const int qt = (gridDim.x - 1) - blockIdx.x;
    const int bh = blockIdx.y;
    const int q0 = qt * 128;
    const __half* Qg = g_q  + (size_t)bh*Ll*QKD + (size_t)q0*QKD;
    const __half* Kg = g_k  + (size_t)bh*Ll*QKD;
    const __half* Vg = g_vt + (size_t)bh*DHh*Ll;

    const int tid  = threadIdx.x;
    const int lane = tid & 31;
    const int warp = tid >> 5;
    const int r = lane >> 2, c = lane & 3;
    const int ln15 = lane & 15;
    const int hi16 = (lane >> 4) * 16;
    const int m0 = warp * 16;

    auto fillKV = [&](int s, int k0) {
        const unsigned kS = sK + s*KST*4;
        const unsigned vS = sV + s*VST*4;
        for (int i = tid; i < 64*24; i += 256) {
            int row = i / 24, ch = i % 24;
            cp16(kS + (row*QS + ch*4)*4, Kg + (size_t)(k0+row)*QKD + ch*8);
        }
        for (int i = tid; i < 128*8; i += 256) {
            int d = i >> 3, ch = i & 7;
            cp16(vS + (d*VS + ch*4)*4, Vg + (size_t)d*Ll + k0 + ch*8);
        }
    };

    for (int i = tid; i < 128*24; i += 256) {
        int row = i / 24, ch = i % 24;
        *(uint4*)&Qs[row*QS + ch*4] = *(const uint4*)(Qg + (size_t)row*QKD + ch*8);
    }

    const int nkt = 2*(qt+1);

    fillKV(0, 0);   CP_COMMIT();
    fillKV(1, 64);  CP_COMMIT();
    __syncthreads();

    // Q fragments -> registers (once)
    const unsigned qbase = sQ + ((m0 + ln15)*QS)*4 + hi16;
    unsigned qf[12][4];
#pragma unroll
    for (int kk = 0; kk < 12; kk++)
        ldsm4(qf[kk], qbase + kk*32);

    const unsigned pbase = sP + ((m0 + ln15)*VS)*4 + hi16;

    float O[16][4];
#pragma unroll
    for (int nb=0; nb<16; nb++)
#pragma unroll
        for (int t2=0; t2<4; t2++) O[nb][t2] = 0.f;
    float m_i[2] = {-1e30f, -1e30f};
    float l_i[2] = {0.f, 0.f};

    for (int kt = 0; kt < nkt; kt++) {
        CP_WAIT(1);
        __syncthreads();                        // single barrier per tile

        if (kt+2 < nkt) fillKV((kt+2)%AST, (kt+2)*64);
        CP_COMMIT();

        const unsigned kS = sK + (kt%AST)*KST*4;
        const unsigned vS = sV + (kt%AST)*VST*4;
        const int k0 = kt*64;

        float S[8][4];
#pragma unroll
        for (int j=0;j<8;j++)
#pragma unroll
            for (int t2=0;t2<4;t2++) S[j][t2]=0.f;

#pragma unroll
        for (int kk = 0; kk < 12; kk++) {
#pragma unroll
            for (int p = 0; p < 4; p++) {
                unsigned bq[4];
                ldsm4(bq, kS + ((p*16 + ln15)*QS)*4 + hi16 + kk*32);
                unsigned b0[2] = {bq[0], bq[2]};
                unsigned b1[2] = {bq[1], bq[3]};
                mma_h16(S[p*2  ], qf[kk], b0);
                mma_h16(S[p*2+1], qf[kk], b1);
            }
        }

        if (kt >= nkt - 2) {
            const int row0 = q0 + m0 + r;
            const int row1 = row0 + 8;
#pragma unroll
            for (int j = 0; j < 8; j++) {
                int col = k0 + j*8 + 2*c;
                if (col   > row0) S[j][0] = -1e30f;
                if (col+1 > row0) S[j][1] = -1e30f;
                if (col   > row1) S[j][2] = -1e30f;
                if (col+1 > row1) S[j][3] = -1e30f;
            }
        }

        float mx0 = -1e30f, mx1 = -1e30f;
#pragma unroll
        for (int j=0;j<8;j++) {
            mx0 = fmaxf(mx0, fmaxf(S[j][0], S[j][1]));
            mx1 = fmaxf(mx1, fmaxf(S[j][2], S[j][3]));
        }
        mx0 = fmaxf(mx0, __shfl_xor_sync(0xffffffffu, mx0, 1));
        mx0 = fmaxf(mx0, __shfl_xor_sync(0xffffffffu, mx0, 2));
        mx1 = fmaxf(mx1, __shfl_xor_sync(0xffffffffu, mx1, 1));
        mx1 = fmaxf(mx1, __shfl_xor_sync(0xffffffffu, mx1, 2));

        float mn0 = fmaxf(m_i[0], mx0), mn1 = fmaxf(m_i[1], mx1);
        float corr0 = __expf(m_i[0]-mn0), corr1 = __expf(m_i[1]-mn1);
        float rs0 = 0.f, rs1 = 0.f;
#pragma unroll
        for (int j=0;j<8;j++) {
            S[j][0] = __expf(S[j][0]-mn0); rs0 += S[j][0];
            S[j][1] = __expf(S[j][1]-mn0); rs0 += S[j][1];
            S[j][2] = __expf(S[j][2]-mn1); rs1 += S[j][2];
            S[j][3] = __expf(S[j][3]-mn1); rs1 += S[j][3];
        }
        rs0 += __shfl_xor_sync(0xffffffffu, rs0, 1);
        rs0 += __shfl_xor_sync(0xffffffffu, rs0, 2);
        rs1 += __shfl_xor_sync(0xffffffffu, rs1, 1);
        rs1 += __shfl_xor_sync(0xffffffffu, rs1, 2);
        l_i[0] = l_i[0]*corr0 + rs0;  m_i[0] = mn0;
        l_i[1] = l_i[1]*corr1 + rs1;  m_i[1] = mn1;

#pragma unroll
        for (int nb=0; nb<16; nb++) {
            O[nb][0]*=corr0; O[nb][1]*=corr0;
            O[nb][2]*=corr1; O[nb][3]*=corr1;
        }

#pragma unroll
        for (int j=0;j<8;j++) {
            __half2 p0 = __floats2half2_rn(S[j][0], S[j][1]);
            __half2 p1 = __floats2half2_rn(S[j][2], S[j][3]);
            Ps[(m0+r  )*VS + j*4 + c] = *(unsigned*)&p0;
            Ps[(m0+r+8)*VS + j*4 + c] = *(unsigned*)&p1;
        }
        __syncwarp();

#pragma unroll
        for (int kk = 0; kk < 4; kk++) {
            unsigned a[4];
            ldsm4(a, pbase + kk*32);
#pragma unroll
            for (int p = 0; p < 8; p++) {
                unsigned bq[4];
                ldsm4(bq, vS + ((p*16 + ln15)*VS)*4 + hi16 + kk*32);
                unsigned b0[2] = {bq[0], bq[2]};
                unsigned b1[2] = {bq[1], bq[3]};
                mma_h16(O[p*2  ], a, b0);
                mma_h16(O[p*2+1], a, b1);
            }
        }
    }

    const int b = bh >> 4, h = bh & 15;
    const float inv0 = 1.0f / l_i[0];
    const float inv1 = 1.0f / l_i[1];
    const int l0 = q0 + m0 + r;
    __half* d0 = g_ao + ((size_t)(b*Ll + l0    ))*Dd + h*DHh;
    __half* d1 = g_ao + ((size_t)(b*Ll + l0 + 8))*Dd + h*DHh;
#pragma unroll
    for (int nb=0; nb<16; nb++) {
        *(__half2*)&d0[nb*8 + 2*c] = __floats2half2_rn(O[nb][0]*inv0, O[nb][1]*inv0);
        *(__half2*)&d1[nb*8 + 2*c] = __floats2half2_rn(O[nb][2]*inv1, O[nb][3]*inv1);
    }
}

// ---------------- launch ----------------
extern "C" void kernel_launch(void* const* d_in, const int* in_sizes, int n_in,
                              void* d_out, int out_size)
{
    const float* x     = (const float*)d_in[0];
    const float* W_DKV = (const float*)d_in[1];
    const float* W_UK  = (const float*)d_in[2];
    const float* W_UV  = (const float*)d_in[3];
    const float* W_DQ  = (const float*)d_in[4];
    const float* W_UQ  = (const float*)d_in[5];
    const float* W_QR  = (const float*)d_in[6];
    const float* W_KR  = (const float*)d_in[7];
    const float* W_O   = (const float*)d_in[8];
    const float* s_qk  = (const float*)d_in[9];
    float* out = (float*)d_out;

    __half *xh, *w1t, *w2t, *w3t, *woT, *c1, *c2, *c3, *ao;
    cudaGetSymbolAddress((void**)&xh,  g_xh);
    cudaGetSymbolAddress((void**)&w1t, g_w1t);
    cudaGetSymbolAddress((void**)&w2t, g_w2t);
    cudaGetSymbolAddress((void**)&w3t, g_w3t);
    cudaGetSymbolAddress((void**)&woT, g_woT);
    cudaGetSymbolAddress((void**)&c1,  g_c1);
    cudaGetSymbolAddress((void**)&c2,  g_c2);
    cudaGetSymbolAddress((void**)&c3,  g_c3);
    cudaGetSymbolAddress((void**)&ao,  g_ao);

    const int gemm_smem = 6*GST*4;                                     // 110592
    cudaFuncSetAttribute(h16_gemm<false>, cudaFuncAttributeMaxDynamicSharedMemorySize, gemm_smem);
    cudaFuncSetAttribute(h16_gemm<true>,  cudaFuncAttributeMaxDynamicSharedMemorySize, gemm_smem);
    const int attn_smem = (128*QS + AST*KST + AST*VST + 128*VS) * 4;   // 201728
    cudaFuncSetAttribute(attn_h16, cudaFuncAttributeMaxDynamicSharedMemorySize, attn_smem);

    dim3 thr(256);

    // 1: fused pre-pass (rope + cvt + weight transposes)
    fused_pre<<<PRE_NBLK, thr>>>(x, W_DKV, W_DQ, W_KR, W_UK, W_UV, W_UQ, W_QR, W_O);

    // 2-4: fused projections (fp16 tensor cores)
    h16_gemm<false><<<dim3((N1+127)/128, Mtok/128), thr, gemm_smem>>>(xh, w1t, c1, N1, Dd, Dd, N1);
    h16_gemm<false><<<dim3(N2/128, Mtok/128), thr, gemm_smem>>>(c1, w2t, c2, N2, DCc, N1, N2);
    h16_gemm<false><<<dim3(N3/128, Mtok/128), thr, gemm_smem>>>(c1 + DCc, w3t, c3, N3, DCc, N1, N3);

    // 5: fused prep (normalize/rope) + V transpose
    prep3<<<Mtok*NHh + 2048, thr>>>(s_qk);

    // 6: attention  (6th launch -> sampled by ncu -s 5 -c 1)
    attn_h16<<<dim3(Ll/128, Bb*NHh), thr, attn_smem>>>();

    // 7: output projection -> d_out (fp32 out)
    h16_gemm<true><<<dim3(Dd/128, Mtok/128), thr, gemm_smem>>>(ao, woT, out, Dd, Dd, Dd, Dd);
}

// round 12
// speedup vs baseline: 1.0232x; 1.0232x over previous
#include <cuda_runtime.h>
#include <cuda_fp16.h>
#include <math.h>

// ---------------- problem constants ----------------
#define Bb 4
#define Ll 2048
#define Dd 2048
#define NHh 16
#define DHh 128
#define DHRr 64
#define DCc 1024
#define Mtok (Bb*Ll)            // 8192
#define QKD 192                 // DH + DHR
#define N1 (DCc + DCc + DHRr)   // 2112 : [ckv | cq | kr]
#define N2 (Dd + Dd)            // 4096 : [kc | vfl]
#define N3 (Dd + NHh*DHRr)      // 3072 : [qc | qr]

// ---------------- device scratch (static, allocation-free) ----------------
__device__ __half g_xh  [(size_t)Mtok*Dd];
__device__ __half g_w1t [(size_t)N1*Dd];
__device__ __half g_w2t [(size_t)N2*DCc];
__device__ __half g_w3t [(size_t)N3*DCc];
__device__ __half g_woT [(size_t)Dd*Dd];
__device__ __half g_c1  [(size_t)Mtok*N1];   // ckv | cq | kr
__device__ __half g_c2  [(size_t)Mtok*N2];   // kc | vfl
__device__ __half g_c3  [(size_t)Mtok*N3];   // qc | qr
__device__ __half g_q   [(size_t)Bb*NHh*Ll*QKD];
__device__ __half g_k   [(size_t)Bb*NHh*Ll*QKD];
__device__ __half g_vt  [(size_t)Bb*NHh*DHh*Ll];   // [bh][d][l]
__device__ __half g_ao  [(size_t)Mtok*Dd];
__device__ float  g_cs  [Ll*32];
__device__ float  g_sn  [Ll*32];

// ---------------- asm helpers ----------------
__device__ __forceinline__ void mma_h16(float* d, const unsigned* a, const unsigned* b) {
    asm volatile(
        "mma.sync.aligned.m16n8k16.row.col.f32.f16.f16.f32 "
        "{%0,%1,%2,%3}, {%4,%5,%6,%7}, {%8,%9}, {%0,%1,%2,%3};"
        : "+f"(d[0]), "+f"(d[1]), "+f"(d[2]), "+f"(d[3])
        : "r"(a[0]), "r"(a[1]), "r"(a[2]), "r"(a[3]), "r"(b[0]), "r"(b[1]));
}

__device__ __forceinline__ unsigned smem_u32(const void* p) {
    return (unsigned)__cvta_generic_to_shared(p);
}

__device__ __forceinline__ void ldsm4(unsigned* r, unsigned addr) {
    asm volatile("ldmatrix.sync.aligned.m8n8.x4.shared.b16 {%0,%1,%2,%3}, [%4];"
        : "=r"(r[0]), "=r"(r[1]), "=r"(r[2]), "=r"(r[3]) : "r"(addr));
}

__device__ __forceinline__ void cp16(unsigned dst, const void* src) {
    asm volatile("cp.async.cg.shared.global [%0], [%1], 16;" :: "r"(dst), "l"(src));
}
#define CP_COMMIT() asm volatile("cp.async.commit_group;")
#define CP_WAIT(N)  asm volatile("cp.async.wait_group %0;" :: "n"(N))

// ---------------- fused pre-pass: rope table + x->fp16 + 8 weight transposes
#define PRE_ROPE 256
#define PRE_CVT  16384
#define PRE_NBLK (PRE_ROPE + PRE_CVT + 2048*5 + 128 + 1024 + 4096)   // 32128
__global__ void __launch_bounds__(256) fused_pre(
    const float* __restrict__ x,
    const float* __restrict__ WDKV, const float* __restrict__ WDQ,
    const float* __restrict__ WKR,  const float* __restrict__ WUK,
    const float* __restrict__ WUV,  const float* __restrict__ WUQ,
    const float* __restrict__ WQR,  const float* __restrict__ WO)
{
    __shared__ __half tsh[32][33];
    int bid = blockIdx.x;
    const int tid = threadIdx.x;

    if (bid < PRE_ROPE) {
        int idx = bid*256 + tid;
        int l = idx >> 5, jj = idx & 31;
        float inv = powf(10000.0f, -(float)jj/32.0f);
        float ang = (float)l * inv;
        g_cs[l*32 + jj] = cosf(ang);
        g_sn[l*32 + jj] = sinf(ang);
        return;
    }
    bid -= PRE_ROPE;
    if (bid < PRE_CVT) {
        int i = bid*256 + tid;
        float4 v = ((const float4*)x)[i];
        __half2* o = (__half2*)g_xh;
        o[2*i]   = __floats2half2_rn(v.x, v.y);
        o[2*i+1] = __floats2half2_rn(v.z, v.w);
        return;
    }
    bid -= PRE_CVT;

    const float* W; __half* Wt; int K, N, t;
    if      (bid <  2048) { W=WDKV; Wt=g_w1t;                   K=Dd;  N=DCc;      t=bid; }
    else if (bid <  4096) { W=WDQ;  Wt=g_w1t+(size_t)DCc*Dd;    K=Dd;  N=DCc;      t=bid-2048; }
    else if (bid <  4224) { W=WKR;  Wt=g_w1t+(size_t)2*DCc*Dd;  K=Dd;  N=DHRr;     t=bid-4096; }
    else if (bid <  6272) { W=WUK;  Wt=g_w2t;                   K=DCc; N=Dd;       t=bid-4224; }
    else if (bid <  8320) { W=WUV;  Wt=g_w2t+(size_t)Dd*DCc;    K=DCc; N=Dd;       t=bid-6272; }
    else if (bid < 10368) { W=WUQ;  Wt=g_w3t;                   K=DCc; N=Dd;       t=bid-8320; }
    else if (bid < 11392) { W=WQR;  Wt=g_w3t+(size_t)Dd*DCc;    K=DCc; N=NHh*DHRr; t=bid-10368; }
    else                  { W=WO;   Wt=g_woT;                   K=Dd;  N=Dd;       t=bid-11392; }

    const int nx = N/32;
    const int n0 = (t % nx)*32, k0 = (t / nx)*32;
    const int tx = tid & 31, ty = tid >> 5;
#pragma unroll
    for (int i=0;i<4;i++)
        tsh[ty+i*8][tx] = __float2half(W[(size_t)(k0+ty+i*8)*N + n0+tx]);
    __syncthreads();
#pragma unroll
    for (int i=0;i<4;i++)
        Wt[(size_t)(n0+ty+i*8)*K + k0+tx] = tsh[tx][ty+i*8];
}

// ---------------- fp16 tensor-core GEMM: C[M][N] = A * Bt^T ----------------
#define SW 36
#define GST (128*SW)
template<bool OUTF32>
__global__ void __launch_bounds__(256, 2)
h16_gemm(const __half* __restrict__ A, const __half* __restrict__ Bt,
         void* __restrict__ Cv, int N, int K, int lda, int ldc)
{
    extern __shared__ unsigned gsm[];
    const unsigned sA = smem_u32(gsm);
    const unsigned sB = sA + 3*GST*4;

    const int tid  = threadIdx.x;
    const int lane = tid & 31;
    const int warp = tid >> 5;
    const int wm = warp >> 2, wn = warp & 3;
    const int ln15 = lane & 15;
    const int hi16 = (lane >> 4) * 16;

    const __half* Ag = A  + (size_t)blockIdx.y * 128 * lda;
    const __half* Bg = Bt + (size_t)blockIdx.x * 128 * K;
    const int nrem = N - blockIdx.x*128;

    unsigned afo[4], bfo[2];
#pragma unroll
    for (int ma=0; ma<4; ma++) afo[ma] = ((wm*64 + ma*16 + ln15)*SW)*4 + hi16;
#pragma unroll
    for (int nb=0; nb<2; nb++) bfo[nb] = ((wn*32 + nb*16 + ln15)*SW)*4 + hi16;

    float acc[4][4][4];
#pragma unroll
    for (int i=0;i<4;i++)
#pragma unroll
        for (int j=0;j<4;j++)
#pragma unroll
            for (int t=0;t<4;t++) acc[i][j][t]=0.f;

    const int nk = K/64;

    auto fill = [&](int s, int k0) {
        const unsigned aB = sA + s*GST*4;
        const unsigned bB = sB + s*GST*4;
#pragma unroll
        for (int i = 0; i < 4; i++) {
            int idx = tid + i*256;
            int row = idx >> 3, ch = idx & 7;
            cp16(aB + row*SW*4 + ch*16, Ag + (size_t)row*lda + k0 + ch*8);
        }
#pragma unroll
        for (int i = 0; i < 4; i++) {
            int idx = tid + i*256;
            int row = idx >> 3, ch = idx & 7;
            int gr = (row < nrem) ? row : (nrem-1);
            cp16(bB + row*SW*4 + ch*16, Bg + (size_t)gr*K + k0 + ch*8);
        }
    };

    fill(0, 0);  CP_COMMIT();
    fill(1, 64); CP_COMMIT();

    for (int kt=0; kt<nk; kt++) {
        CP_WAIT(1);
        __syncthreads();

        const int kn = kt+2;
        if (kn < nk) fill(kn % 3, kn*64);
        CP_COMMIT();

        const unsigned aS = sA + (kt%3)*GST*4;
        const unsigned bS = sB + (kt%3)*GST*4;
#pragma unroll
        for (int kc8 = 0; kc8 < 32; kc8 += 8) {
            unsigned af[4][4];
#pragma unroll
            for (int ma=0;ma<4;ma++)
                ldsm4(af[ma], aS + afo[ma] + kc8*4);
#pragma unroll
            for (int nb=0;nb<2;nb++) {
                unsigned bq[4];
                ldsm4(bq, bS + bfo[nb] + kc8*4);
                unsigned b0[2] = {bq[0], bq[2]};
                unsigned b1[2] = {bq[1], bq[3]};
#pragma unroll
                for (int ma=0;ma<4;ma++) {
                    mma_h16(acc[ma][nb*2  ], af[ma], b0);
                    mma_h16(acc[ma][nb*2+1], af[ma], b1);
                }
            }
        }
    }

    const int r = lane >> 2, c = lane & 3;
#pragma unroll
    for (int ma=0;ma<4;ma++) {
        int m = blockIdx.y*128 + wm*64 + ma*16 + r;
#pragma unroll
        for (int na=0;na<4;na++) {
            int n = blockIdx.x*128 + wn*32 + na*8 + 2*c;
            if (n < N) {
                if (OUTF32) {
                    float* C = (float*)Cv;
                    *(float2*)&C[(size_t)m*ldc + n]     = make_float2(acc[ma][na][0], acc[ma][na][1]);
                    *(float2*)&C[(size_t)(m+8)*ldc + n] = make_float2(acc[ma][na][2], acc[ma][na][3]);
                } else {
                    __half* C = (__half*)Cv;
                    *(__half2*)&C[(size_t)m*ldc + n]     = __floats2half2_rn(acc[ma][na][0], acc[ma][na][1]);
                    *(__half2*)&C[(size_t)(m+8)*ldc + n] = __floats2half2_rn(acc[ma][na][2], acc[ma][na][3]);
                }
            }
        }
    }
}

// ---------------- prep3: fused (RoPE+concat+normalize) and V-transpose -----
__global__ void __launch_bounds__(256) prep3(const float* __restrict__ s_qk_ptr)
{
    __shared__ float red[2][6];
    __shared__ __half tv[64][DHh+8];

    int bid = blockIdx.x;
    const int t = threadIdx.x;

    if (bid < Mtok*NHh) {
        const int bl = bid & (Mtok-1);
        const int h  = bid >> 13;
        const int b = bl >> 11, l = bl & 2047;
        const float s_qk = *s_qk_ptr;

        float kv = 0.f, qv = 0.f;
        if (t < 128) {
            kv = __half2float(g_c2[(size_t)bl*N2 + h*DHh + t]);
            qv = __half2float(g_c3[(size_t)bl*N3 + h*DHh + t]);
        } else if (t < 192) {
            int j = t - 128, jj = j & 31;
            float csv = g_cs[l*32 + jj];
            float snv = g_sn[l*32 + jj];
            {
                const __half* krp = g_c1 + (size_t)bl*N1 + 2*DCc;
                float v  = __half2float(krp[j]);
                float vo = __half2float(krp[(j<32 ? j+32 : j-32)]);
                float rot = (j<32) ? -vo : vo;
                kv = v*csv + rot*snv;
            }
            {
                const __half* qrp = g_c3 + (size_t)bl*N3 + Dd + h*DHRr;
                float v  = __half2float(qrp[j]);
                float vo = __half2float(qrp[(j<32 ? j+32 : j-32)]);
                float rot = (j<32) ? -vo : vo;
                qv = v*csv + rot*snv;
            }
        }

        float ks = kv*kv, qs = qv*qv;
#pragma unroll
        for (int o=16;o>0;o>>=1) {
            ks += __shfl_xor_sync(0xffffffffu, ks, o);
            qs += __shfl_xor_sync(0xffffffffu, qs, o);
        }
        const int w = t >> 5;
        if ((t & 31) == 0 && w < 6) { red[0][w] = ks; red[1][w] = qs; }
        __syncthreads();
        if (t < 192) {
            float ksum = red[0][0]+red[0][1]+red[0][2]+red[0][3]+red[0][4]+red[0][5];
            float qsum = red[1][0]+red[1][1]+red[1][2]+red[1][3]+red[1][4]+red[1][5];
            float invk = 1.0f / fmaxf(sqrtf(ksum), 1e-12f);
            float invq = s_qk / fmaxf(sqrtf(qsum), 1e-12f);
            size_t off = ((size_t)(b*NHh + h)*Ll + l)*QKD + t;
            g_k[off] = __float2half(kv*invk);
            g_q[off] = __float2half(qv*invq);
        }
        return;
    }

    const int vb = bid - Mtok*NHh;
    const int bh = vb >> 5, lxb = vb & 31;
    const int b = bh >> 4, h = bh & 15;
    const int l0 = lxb * 64;

    for (int i = t; i < 64*16; i += 256) {
        int l = i >> 4, ch = i & 15;
        *(uint4*)&tv[l][ch*8] =
            *(const uint4*)(g_c2 + ((size_t)(b*Ll + l0 + l))*N2 + Dd + h*DHh + ch*8);
    }
    __syncthreads();
    for (int i = t; i < 128*8; i += 256) {
        int d = i >> 3, ch = i & 7;
        __half2 p[4];
#pragma unroll
        for (int u=0;u<4;u++) {
            int l = ch*8 + u*2;
            p[u] = __halves2half2(tv[l][d], tv[l+1][d]);
        }
        *(uint4*)(g_vt + (size_t)bh*DHh*Ll + (size_t)d*Ll + l0 + ch*8) = *(uint4*)p;
    }
}

// ---------------- fp16 flash attention (causal, BQ=256, BK=64) -------------
// 16 warps (512 thr), warp-local softmax, P kept in registers (acc->A frag
// identity), 2-stage K/V cp.async ring with one barrier per tile.
#define QS 100
#define VS 36
#define KST (64*QS)
#define VST (128*VS)
#define BQA 256
__global__ void __launch_bounds__(512, 1) attn_h16()
{
    extern __shared__ unsigned smu[];
    const unsigned sQ = smem_u32(smu);          // [256][100]
    const unsigned sK = sQ + BQA*QS*4;          // 2 stages [64][100]
    const unsigned sV = sK + 2*KST*4;           // 2 stages [128][36]

    const int qt = (gridDim.x - 1) - blockIdx.x;   // heavy blocks first
    const int bh = blockIdx.y;
    const int q0 = qt * BQA;
    const __half* Qg = g_q  + (size_t)bh*Ll*QKD + (size_t)q0*QKD;
    const __half* Kg = g_k  + (size_t)bh*Ll*QKD;
    const __half* Vg = g_vt + (size_t)bh*DHh*Ll;

    const int tid  = threadIdx.x;
    const int lane = tid & 31;
    const int warp = tid >> 5;
    const int r = lane >> 2, c = lane & 3;
    const int ln15 = lane & 15;
    const int hi16 = (lane >> 4) * 16;
    const int m0 = warp * 16;

    auto fillKV = [&](int s, int k0) {
        const unsigned kS = sK + s*KST*4;
        const unsigned vS = sV + s*VST*4;
        for (int i = tid; i < 64*24; i += 512) {
            int row = i / 24, ch = i % 24;
            cp16(kS + (row*QS + ch*4)*4, Kg + (size_t)(k0+row)*QKD + ch*8);
        }
        for (int i = tid; i < 128*8; i += 512) {
            int d = i >> 3, ch = i & 7;
            cp16(vS + (d*VS + ch*4)*4, Vg + (size_t)d*Ll + k0 + ch*8);
        }
    };

    // Q tile -> smem (once)
    for (int i = tid; i < BQA*24; i += 512) {
        int row = i / 24, ch = i % 24;
        *(uint4*)&smu[row*QS + ch*4] = *(const uint4*)(Qg + (size_t)row*QKD + ch*8);
    }
    fillKV(0, 0);
    CP_COMMIT();

    const unsigned qbase = sQ + ((m0 + ln15)*QS)*4 + hi16;

    float O[16][4];
#pragma unroll
    for (int nb=0; nb<16; nb++)
#pragma unroll
        for (int t2=0; t2<4; t2++) O[nb][t2] = 0.f;
    float m_i[2] = {-1e30f, -1e30f};
    float l_i[2] = {0.f, 0.f};

    const int nkt = 4*(qt+1);

    for (int kt = 0; kt < nkt; kt++) {
        CP_WAIT(0);
        __syncthreads();                       // Q visible (kt=0) + prev stage free
        if (kt+1 < nkt) fillKV((kt+1)&1, (kt+1)*64);
        CP_COMMIT();

        const int k0 = kt*64;
        const bool active = (k0 <= q0 + m0 + 15);   // skip fully-masked tiles
        if (active) {
            const unsigned kS = sK + (kt&1)*KST*4;
            const unsigned vS = sV + (kt&1)*VST*4;

            // ---- S = Q K^T ----
            float S[8][4];
#pragma unroll
            for (int j=0;j<8;j++)
#pragma unroll
                for (int t2=0;t2<4;t2++) S[j][t2]=0.f;

#pragma unroll
            for (int kk = 0; kk < 12; kk++) {
                unsigned a[4];
                ldsm4(a, qbase + kk*32);
#pragma unroll
                for (int p = 0; p < 4; p++) {
                    unsigned bq[4];
                    ldsm4(bq, kS + ((p*16 + ln15)*QS)*4 + hi16 + kk*32);
                    unsigned b0[2] = {bq[0], bq[2]};
                    unsigned b1[2] = {bq[1], bq[3]};
                    mma_h16(S[p*2  ], a, b0);
                    mma_h16(S[p*2+1], a, b1);
                }
            }

            // ---- causal mask (tiles overlapping this warp's rows) ----
            if (k0 + 63 > q0 + m0) {
                const int row0 = q0 + m0 + r;
                const int row1 = row0 + 8;
#pragma unroll
                for (int j = 0; j < 8; j++) {
                    int col = k0 + j*8 + 2*c;
                    if (col   > row0) S[j][0] = -1e30f;
                    if (col+1 > row0) S[j][1] = -1e30f;
                    if (col   > row1) S[j][2] = -1e30f;
                    if (col+1 > row1) S[j][3] = -1e30f;
                }
            }

            // ---- online softmax (warp-local rows r, r+8) ----
            float mx0 = -1e30f, mx1 = -1e30f;
#pragma unroll
            for (int j=0;j<8;j++) {
                mx0 = fmaxf(mx0, fmaxf(S[j][0], S[j][1]));
                mx1 = fmaxf(mx1, fmaxf(S[j][2], S[j][3]));
            }
            mx0 = fmaxf(mx0, __shfl_xor_sync(0xffffffffu, mx0, 1));
            mx0 = fmaxf(mx0, __shfl_xor_sync(0xffffffffu, mx0, 2));
            mx1 = fmaxf(mx1, __shfl_xor_sync(0xffffffffu, mx1, 1));
            mx1 = fmaxf(mx1, __shfl_xor_sync(0xffffffffu, mx1, 2));

            float mn0 = fmaxf(m_i[0], mx0), mn1 = fmaxf(m_i[1], mx1);
            float corr0 = __expf(m_i[0]-mn0), corr1 = __expf(m_i[1]-mn1);
            float rs0 = 0.f, rs1 = 0.f;
#pragma unroll
            for (int j=0;j<8;j++) {
                S[j][0] = __expf(S[j][0]-mn0); rs0 += S[j][0];
                S[j][1] = __expf(S[j][1]-mn0); rs0 += S[j][1];
                S[j][2] = __expf(S[j][2]-mn1); rs1 += S[j][2];
                S[j][3] = __expf(S[j][3]-mn1); rs1 += S[j][3];
            }
            rs0 += __shfl_xor_sync(0xffffffffu, rs0, 1);
            rs0 += __shfl_xor_sync(0xffffffffu, rs0, 2);
            rs1 += __shfl_xor_sync(0xffffffffu, rs1, 1);
            rs1 += __shfl_xor_sync(0xffffffffu, rs1, 2);
            l_i[0] = l_i[0]*corr0 + rs0;  m_i[0] = mn0;
            l_i[1] = l_i[1]*corr1 + rs1;  m_i[1] = mn1;

#pragma unroll
            for (int nb=0; nb<16; nb++) {
                O[nb][0]*=corr0; O[nb][1]*=corr0;
                O[nb][2]*=corr1; O[nb][3]*=corr1;
            }

            // ---- P fragments directly from S accumulators (no smem) ----
#pragma unroll
            for (int kk = 0; kk < 4; kk++) {
                unsigned pa[4];
                {
                    __half2 h0 = __floats2half2_rn(S[2*kk  ][0], S[2*kk  ][1]);
                    __half2 h1 = __floats2half2_rn(S[2*kk  ][2], S[2*kk  ][3]);
                    __half2 h2 = __floats2half2_rn(S[2*kk+1][0], S[2*kk+1][1]);
                    __half2 h3 = __floats2half2_rn(S[2*kk+1][2], S[2*kk+1][3]);
                    pa[0] = *(unsigned*)&h0;
                    pa[1] = *(unsigned*)&h1;
                    pa[2] = *(unsigned*)&h2;
                    pa[3] = *(unsigned*)&h3;
                }
#pragma unroll
                for (int p = 0; p < 8; p++) {
                    unsigned bq[4];
                    ldsm4(bq, vS + ((p*16 + ln15)*VS)*4 + hi16 + kk*32);
                    unsigned b0[2] = {bq[0], bq[2]};
                    unsigned b1[2] = {bq[1], bq[3]};
                    mma_h16(O[p*2  ], pa, b0);
                    mma_h16(O[p*2+1], pa, b1);
                }
            }
        }
    }

    // ---- epilogue ----
    const int b = bh >> 4, h = bh & 15;
    const float inv0 = 1.0f / l_i[0];
    const float inv1 = 1.0f / l_i[1];
    const int l0 = q0 + m0 + r;
    __half* d0 = g_ao + ((size_t)(b*Ll + l0    ))*Dd + h*DHh;
    __half* d1 = g_ao + ((size_t)(b*Ll + l0 + 8))*Dd + h*DHh;
#pragma unroll
    for (int nb=0; nb<16; nb++) {
        *(__half2*)&d0[nb*8 + 2*c] = __floats2half2_rn(O[nb][0]*inv0, O[nb][1]*inv0);
        *(__half2*)&d1[nb*8 + 2*c] = __floats2half2_rn(O[nb][2]*inv1, O[nb][3]*inv1);
    }
}

// ---------------- launch ----------------
extern "C" void kernel_launch(void* const* d_in, const int* in_sizes, int n_in,
                              void* d_out, int out_size)
{
    const float* x     = (const float*)d_in[0];
    const float* W_DKV = (const float*)d_in[1];
    const float* W_UK  = (const float*)d_in[2];
    const float* W_UV  = (const float*)d_in[3];
    const float* W_DQ  = (const float*)d_in[4];
    const float* W_UQ  = (const float*)d_in[5];
    const float* W_QR  = (const float*)d_in[6];
    const float* W_KR  = (const float*)d_in[7];
    const float* W_O   = (const float*)d_in[8];
    const float* s_qk  = (const float*)d_in[9];
    float* out = (float*)d_out;

    __half *xh, *w1t, *w2t, *w3t, *woT, *c1, *c2, *c3, *ao;
    cudaGetSymbolAddress((void**)&xh,  g_xh);
    cudaGetSymbolAddress((void**)&w1t, g_w1t);
    cudaGetSymbolAddress((void**)&w2t, g_w2t);
    cudaGetSymbolAddress((void**)&w3t, g_w3t);
    cudaGetSymbolAddress((void**)&woT, g_woT);
    cudaGetSymbolAddress((void**)&c1,  g_c1);
    cudaGetSymbolAddress((void**)&c2,  g_c2);
    cudaGetSymbolAddress((void**)&c3,  g_c3);
    cudaGetSymbolAddress((void**)&ao,  g_ao);

    const int gemm_smem = 6*GST*4;                              // 110592
    cudaFuncSetAttribute(h16_gemm<false>, cudaFuncAttributeMaxDynamicSharedMemorySize, gemm_smem);
    cudaFuncSetAttribute(h16_gemm<true>,  cudaFuncAttributeMaxDynamicSharedMemorySize, gemm_smem);
    const int attn_smem = (BQA*QS + 2*KST + 2*VST) * 4;         // 190464
    cudaFuncSetAttribute(attn_h16, cudaFuncAttributeMaxDynamicSharedMemorySize, attn_smem);

    dim3 thr(256);

    // 1: fused pre-pass
    fused_pre<<<PRE_NBLK, thr>>>(x, W_DKV, W_DQ, W_KR, W_UK, W_UV, W_UQ, W_QR, W_O);

    // 2-4: fused projections
    h16_gemm<false><<<dim3((N1+127)/128, Mtok/128), thr, gemm_smem>>>(xh, w1t, c1, N1, Dd, Dd, N1);
    h16_gemm<false><<<dim3(N2/128, Mtok/128), thr, gemm_smem>>>(c1, w2t, c2, N2, DCc, N1, N2);
    h16_gemm<false><<<dim3(N3/128, Mtok/128), thr, gemm_smem>>>(c1 + DCc, w3t, c3, N3, DCc, N1, N3);

    // 5: prep + V transpose
    prep3<<<Mtok*NHh + 2048, thr>>>(s_qk);

    // 6: attention (BQ=256, 512 threads)
    attn_h16<<<dim3(Ll/BQA, Bb*NHh), 512, attn_smem>>>();

    // 7: output projection -> d_out
    h16_gemm<true><<<dim3(Dd/128, Mtok/128), thr, gemm_smem>>>(ao, woT, out, Dd, Dd, Dd, Dd);
}

// round 14
// speedup vs baseline: 1.1047x; 1.0797x over previous
#include <cuda_runtime.h>
#include <cuda_fp16.h>
#include <math.h>

// ---------------- problem constants ----------------
#define Bb 4
#define Ll 2048
#define Dd 2048
#define NHh 16
#define DHh 128
#define DHRr 64
#define DCc 1024
#define Mtok (Bb*Ll)            // 8192
#define QKD 192                 // DH + DHR
#define N1 (DCc + DCc + DHRr)   // 2112 : [ckv | cq | kr]
#define N2 (Dd + Dd)            // 4096 : [kc | vfl]
#define N3 (Dd + NHh*DHRr)      // 3072 : [qc | qr]

// ---------------- device scratch (static, allocation-free) ----------------
__device__ __half g_xh  [(size_t)Mtok*Dd];
__device__ __half g_w1t [(size_t)N1*Dd];
__device__ __half g_w2t [(size_t)N2*DCc];
__device__ __half g_w3t [(size_t)N3*DCc];
__device__ __half g_woT [(size_t)Dd*Dd];
__device__ __half g_c1  [(size_t)Mtok*N1];   // ckv | cq | kr
__device__ __half g_c2  [(size_t)Mtok*N2];   // kc | vfl
__device__ __half g_c3  [(size_t)Mtok*N3];   // qc | qr
__device__ __half g_q   [(size_t)Bb*NHh*Ll*QKD];
__device__ __half g_k   [(size_t)Bb*NHh*Ll*QKD];
__device__ __half g_vt  [(size_t)Bb*NHh*DHh*Ll];   // [bh][d][l]
__device__ __half g_ao  [(size_t)Mtok*Dd];
__device__ float  g_cs  [Ll*32];
__device__ float  g_sn  [Ll*32];

// ---------------- asm helpers ----------------
__device__ __forceinline__ void mma_h16(float* d, const unsigned* a, const unsigned* b) {
    asm volatile(
        "mma.sync.aligned.m16n8k16.row.col.f32.f16.f16.f32 "
        "{%0,%1,%2,%3}, {%4,%5,%6,%7}, {%8,%9}, {%0,%1,%2,%3};"
        : "+f"(d[0]), "+f"(d[1]), "+f"(d[2]), "+f"(d[3])
        : "r"(a[0]), "r"(a[1]), "r"(a[2]), "r"(a[3]), "r"(b[0]), "r"(b[1]));
}

__device__ __forceinline__ unsigned smem_u32(const void* p) {
    return (unsigned)__cvta_generic_to_shared(p);
}

__device__ __forceinline__ void ldsm4(unsigned* r, unsigned addr) {
    asm volatile("ldmatrix.sync.aligned.m8n8.x4.shared.b16 {%0,%1,%2,%3}, [%4];"
        : "=r"(r[0]), "=r"(r[1]), "=r"(r[2]), "=r"(r[3]) : "r"(addr));
}

__device__ __forceinline__ void cp16(unsigned dst, const void* src) {
    asm volatile("cp.async.cg.shared.global [%0], [%1], 16;" :: "r"(dst), "l"(src));
}
#define CP_COMMIT() asm volatile("cp.async.commit_group;")
#define CP_WAIT(N)  asm volatile("cp.async.wait_group %0;" :: "n"(N))

// ---------------- fused pre-pass: rope table + x->fp16 + 8 weight transposes
#define PRE_ROPE 256
#define PRE_CVT  16384
#define PRE_NBLK (PRE_ROPE + PRE_CVT + 2048*5 + 128 + 1024 + 4096)   // 32128
__global__ void __launch_bounds__(256) fused_pre(
    const float* __restrict__ x,
    const float* __restrict__ WDKV, const float* __restrict__ WDQ,
    const float* __restrict__ WKR,  const float* __restrict__ WUK,
    const float* __restrict__ WUV,  const float* __restrict__ WUQ,
    const float* __restrict__ WQR,  const float* __restrict__ WO)
{
    __shared__ __half tsh[32][33];
    int bid = blockIdx.x;
    const int tid = threadIdx.x;

    if (bid < PRE_ROPE) {
        int idx = bid*256 + tid;
        int l = idx >> 5, jj = idx & 31;
        float inv = powf(10000.0f, -(float)jj/32.0f);
        float ang = (float)l * inv;
        g_cs[l*32 + jj] = cosf(ang);
        g_sn[l*32 + jj] = sinf(ang);
        return;
    }
    bid -= PRE_ROPE;
    if (bid < PRE_CVT) {
        int i = bid*256 + tid;
        float4 v = ((const float4*)x)[i];
        __half2* o = (__half2*)g_xh;
        o[2*i]   = __floats2half2_rn(v.x, v.y);
        o[2*i+1] = __floats2half2_rn(v.z, v.w);
        return;
    }
    bid -= PRE_CVT;

    const float* W; __half* Wt; int K, N, t;
    if      (bid <  2048) { W=WDKV; Wt=g_w1t;                   K=Dd;  N=DCc;      t=bid; }
    else if (bid <  4096) { W=WDQ;  Wt=g_w1t+(size_t)DCc*Dd;    K=Dd;  N=DCc;      t=bid-2048; }
    else if (bid <  4224) { W=WKR;  Wt=g_w1t+(size_t)2*DCc*Dd;  K=Dd;  N=DHRr;     t=bid-4096; }
    else if (bid <  6272) { W=WUK;  Wt=g_w2t;                   K=DCc; N=Dd;       t=bid-4224; }
    else if (bid <  8320) { W=WUV;  Wt=g_w2t+(size_t)Dd*DCc;    K=DCc; N=Dd;       t=bid-6272; }
    else if (bid < 10368) { W=WUQ;  Wt=g_w3t;                   K=DCc; N=Dd;       t=bid-8320; }
    else if (bid < 11392) { W=WQR;  Wt=g_w3t+(size_t)Dd*DCc;    K=DCc; N=NHh*DHRr; t=bid-10368; }
    else                  { W=WO;   Wt=g_woT;                   K=Dd;  N=Dd;       t=bid-11392; }

    const int nx = N/32;
    const int n0 = (t % nx)*32, k0 = (t / nx)*32;
    const int tx = tid & 31, ty = tid >> 5;
#pragma unroll
    for (int i=0;i<4;i++)
        tsh[ty+i*8][tx] = __float2half(W[(size_t)(k0+ty+i*8)*N + n0+tx]);
    __syncthreads();
#pragma unroll
    for (int i=0;i<4;i++)
        Wt[(size_t)(n0+ty+i*8)*K + k0+tx] = tsh[tx][ty+i*8];
}

// ---------------- fp16 tensor-core GEMM body (shared by kernels) -----------
#define SW 36
#define GST (128*SW)
template<bool OUTF32>
__device__ __forceinline__ void gemm_body(
    const __half* __restrict__ A, const __half* __restrict__ Bt,
    void* __restrict__ Cv, int N, int K, int lda, int ldc,
    int bx, int by, unsigned sA)
{
    const unsigned sB = sA + 3*GST*4;

    const int tid  = threadIdx.x;
    const int lane = tid & 31;
    const int warp = tid >> 5;
    const int wm = warp >> 2, wn = warp & 3;
    const int ln15 = lane & 15;
    const int hi16 = (lane >> 4) * 16;

    const __half* Ag = A  + (size_t)by * 128 * lda;
    const __half* Bg = Bt + (size_t)bx * 128 * K;
    const int nrem = N - bx*128;

    unsigned afo[4], bfo[2];
#pragma unroll
    for (int ma=0; ma<4; ma++) afo[ma] = ((wm*64 + ma*16 + ln15)*SW)*4 + hi16;
#pragma unroll
    for (int nb=0; nb<2; nb++) bfo[nb] = ((wn*32 + nb*16 + ln15)*SW)*4 + hi16;

    float acc[4][4][4];
#pragma unroll
    for (int i=0;i<4;i++)
#pragma unroll
        for (int j=0;j<4;j++)
#pragma unroll
            for (int t=0;t<4;t++) acc[i][j][t]=0.f;

    const int nk = K/64;

    auto fill = [&](int s, int k0) {
        const unsigned aB = sA + s*GST*4;
        const unsigned bB = sB + s*GST*4;
#pragma unroll
        for (int i = 0; i < 4; i++) {
            int idx = tid + i*256;
            int row = idx >> 3, ch = idx & 7;
            cp16(aB + row*SW*4 + ch*16, Ag + (size_t)row*lda + k0 + ch*8);
        }
#pragma unroll
        for (int i = 0; i < 4; i++) {
            int idx = tid + i*256;
            int row = idx >> 3, ch = idx & 7;
            int gr = (row < nrem) ? row : (nrem-1);
            cp16(bB + row*SW*4 + ch*16, Bg + (size_t)gr*K + k0 + ch*8);
        }
    };

    fill(0, 0);  CP_COMMIT();
    fill(1, 64); CP_COMMIT();

    for (int kt=0; kt<nk; kt++) {
        CP_WAIT(1);
        __syncthreads();

        const int kn = kt+2;
        if (kn < nk) fill(kn % 3, kn*64);
        CP_COMMIT();

        const unsigned aS = sA + (kt%3)*GST*4;
        const unsigned bS = sB + (kt%3)*GST*4;
#pragma unroll
        for (int kc8 = 0; kc8 < 32; kc8 += 8) {
            unsigned af[4][4];
#pragma unroll
            for (int ma=0;ma<4;ma++)
                ldsm4(af[ma], aS + afo[ma] + kc8*4);
#pragma unroll
            for (int nb=0;nb<2;nb++) {
                unsigned bq[4];
                ldsm4(bq, bS + bfo[nb] + kc8*4);
                unsigned b0[2] = {bq[0], bq[2]};
                unsigned b1[2] = {bq[1], bq[3]};
#pragma unroll
                for (int ma=0;ma<4;ma++) {
                    mma_h16(acc[ma][nb*2  ], af[ma], b0);
                    mma_h16(acc[ma][nb*2+1], af[ma], b1);
                }
            }
        }
    }

    const int r = lane >> 2, c = lane & 3;
#pragma unroll
    for (int ma=0;ma<4;ma++) {
        int m = by*128 + wm*64 + ma*16 + r;
#pragma unroll
        for (int na=0;na<4;na++) {
            int n = bx*128 + wn*32 + na*8 + 2*c;
            if (n < N) {
                if (OUTF32) {
                    float* C = (float*)Cv;
                    *(float2*)&C[(size_t)m*ldc + n]     = make_float2(acc[ma][na][0], acc[ma][na][1]);
                    *(float2*)&C[(size_t)(m+8)*ldc + n] = make_float2(acc[ma][na][2], acc[ma][na][3]);
                } else {
                    __half* C = (__half*)Cv;
                    *(__half2*)&C[(size_t)m*ldc + n]     = __floats2half2_rn(acc[ma][na][0], acc[ma][na][1]);
                    *(__half2*)&C[(size_t)(m+8)*ldc + n] = __floats2half2_rn(acc[ma][na][2], acc[ma][na][3]);
                }
            }
        }
    }
}

template<bool OUTF32>
__global__ void __launch_bounds__(256, 2)
h16_gemm(const __half* __restrict__ A, const __half* __restrict__ Bt,
         void* __restrict__ Cv, int N, int K, int lda, int ldc)
{
    extern __shared__ unsigned gsm[];
    gemm_body<OUTF32>(A, Bt, Cv, N, K, lda, ldc, blockIdx.x, blockIdx.y, smem_u32(gsm));
}

// fused g2+g3: x-blocks [0,32) -> c1*w2t->c2 ; [32,56) -> (c1+DCc)*w3t->c3
__global__ void __launch_bounds__(256, 2)
h16_gemm23(const __half* __restrict__ c1, const __half* __restrict__ w2t,
           const __half* __restrict__ w3t, __half* __restrict__ c2,
           __half* __restrict__ c3)
{
    extern __shared__ unsigned gsm[];
    const int bx = blockIdx.x;
    if (bx < N2/128)
        gemm_body<false>(c1, w2t, c2, N2, DCc, N1, N2, bx, blockIdx.y, smem_u32(gsm));
    else
        gemm_body<false>(c1 + DCc, w3t, c3, N3, DCc, N1, N3, bx - N2/128, blockIdx.y, smem_u32(gsm));
}

// ---------------- prep4: warp-per-(token,head) RoPE+normalize; + V-transpose
#define PREP_WBLK (Mtok*NHh/8)     // 16384
__global__ void __launch_bounds__(256) prep4(const float* __restrict__ s_qk_ptr)
{
    __shared__ __half tv[64][DHh+8];
    int bid = blockIdx.x;
    const int tid = threadIdx.x;

    if (bid < PREP_WBLK) {
        const int lane = tid & 31, warp = tid >> 5;
        const int id = bid*8 + warp;               // (token,head) id
        const int bl = id & (Mtok-1);
        const int h  = id >> 13;
        const int b = bl >> 11, l = bl & 2047;
        const float s_qk = *s_qk_ptr;

        float kv[6], qv[6];
#pragma unroll
        for (int i=0;i<4;i++) {
            int t = lane + 32*i;
            kv[i] = __half2float(g_c2[(size_t)bl*N2 + h*DHh + t]);
            qv[i] = __half2float(g_c3[(size_t)bl*N3 + h*DHh + t]);
        }
        {
            float csv = g_cs[l*32 + lane];
            float snv = g_sn[l*32 + lane];
            const __half* krp = g_c1 + (size_t)bl*N1 + 2*DCc;
            const __half* qrp = g_c3 + (size_t)bl*N3 + Dd + h*DHRr;
            // t=128+lane: j=lane<32 -> rot = -v[j+32]
            kv[4] = __half2float(krp[lane])*csv    - __half2float(krp[lane+32])*snv;
            qv[4] = __half2float(qrp[lane])*csv    - __half2float(qrp[lane+32])*snv;
            // t=160+lane: j=lane+32 -> rot = +v[j-32]
            kv[5] = __half2float(krp[lane+32])*csv + __half2float(krp[lane])*snv;
            qv[5] = __half2float(qrp[lane+32])*csv + __half2float(qrp[lane])*snv;
        }

        float ks = 0.f, qs = 0.f;
#pragma unroll
        for (int i=0;i<6;i++) { ks += kv[i]*kv[i]; qs += qv[i]*qv[i]; }
#pragma unroll
        for (int o=16;o>0;o>>=1) {
            ks += __shfl_xor_sync(0xffffffffu, ks, o);
            qs += __shfl_xor_sync(0xffffffffu, qs, o);
        }
        float invk = 1.0f / fmaxf(sqrtf(ks), 1e-12f);
        float invq = s_qk / fmaxf(sqrtf(qs), 1e-12f);

        size_t off = ((size_t)(b*NHh + h)*Ll + l)*QKD;
#pragma unroll
        for (int i=0;i<6;i++) {
            int t = lane + 32*i;
            g_k[off + t] = __float2half(kv[i]*invk);
            g_q[off + t] = __float2half(qv[i]*invq);
        }
        return;
    }

    // ---- vtrans region ----
    const int vb = bid - PREP_WBLK;
    const int bh = vb >> 5, lxb = vb & 31;
    const int b = bh >> 4, h = bh & 15;
    const int l0 = lxb * 64;

    for (int i = tid; i < 64*16; i += 256) {
        int l = i >> 4, ch = i & 15;
        *(uint4*)&tv[l][ch*8] =
            *(const uint4*)(g_c2 + ((size_t)(b*Ll + l0 + l))*N2 + Dd + h*DHh + ch*8);
    }
    __syncthreads();
    for (int i = tid; i < 128*8; i += 256) {
        int d = i >> 3, ch = i & 7;
        __half2 p[4];
#pragma unroll
        for (int u=0;u<4;u++) {
            int l = ch*8 + u*2;
            p[u] = __halves2half2(tv[l][d], tv[l+1][d]);
        }
        *(uint4*)(g_vt + (size_t)bh*DHh*Ll + (size_t)d*Ll + l0 + ch*8) = *(uint4*)p;
    }
}

// ---------------- fp16 flash attention (causal, BQ=256, BK=64) -------------
#define QS 100
#define VS 36
#define KST (64*QS)
#define VST (128*VS)
#define BQA 256
__global__ void __launch_bounds__(512, 1) attn_h16()
{
    extern __shared__ unsigned smu[];
    const unsigned sQ = smem_u32(smu);          // [256][100]
    const unsigned sK = sQ + BQA*QS*4;          // 2 stages [64][100]
    const unsigned sV = sK + 2*KST*4;           // 2 stages [128][36]

    const int qt = (gridDim.x - 1) - blockIdx.x;
    const int bh = blockIdx.y;
    const int q0 = qt * BQA;
    const __half* Qg = g_q  + (size_t)bh*Ll*QKD + (size_t)q0*QKD;
    const __half* Kg = g_k  + (size_t)bh*Ll*QKD;
    const __half* Vg = g_vt + (size_t)bh*DHh*Ll;

    const int tid  = threadIdx.x;
    const int lane = tid & 31;
    const int warp = tid >> 5;
    const int r = lane >> 2, c = lane & 3;
    const int ln15 = lane & 15;
    const int hi16 = (lane >> 4) * 16;
    const int m0 = warp * 16;

    auto fillKV = [&](int s, int k0) {
        const unsigned kS = sK + s*KST*4;
        const unsigned vS = sV + s*VST*4;
        for (int i = tid; i < 64*24; i += 512) {
            int row = i / 24, ch = i % 24;
            cp16(kS + (row*QS + ch*4)*4, Kg + (size_t)(k0+row)*QKD + ch*8);
        }
        for (int i = tid; i < 128*8; i += 512) {
            int d = i >> 3, ch = i & 7;
            cp16(vS + (d*VS + ch*4)*4, Vg + (size_t)d*Ll + k0 + ch*8);
        }
    };

    for (int i = tid; i < BQA*24; i += 512) {
        int row = i / 24, ch = i % 24;
        *(uint4*)&smu[row*QS + ch*4] = *(const uint4*)(Qg + (size_t)row*QKD + ch*8);
    }
    fillKV(0, 0);
    CP_COMMIT();

    const unsigned qbase = sQ + ((m0 + ln15)*QS)*4 + hi16;

    float O[16][4];
#pragma unroll
    for (int nb=0; nb<16; nb++)
#pragma unroll
        for (int t2=0; t2<4; t2++) O[nb][t2] = 0.f;
    float m_i[2] = {-1e30f, -1e30f};
    float l_i[2] = {0.f, 0.f};

    const int nkt = 4*(qt+1);

    for (int kt = 0; kt < nkt; kt++) {
        CP_WAIT(0);
        __syncthreads();
        if (kt+1 < nkt) fillKV((kt+1)&1, (kt+1)*64);
        CP_COMMIT();

        const int k0 = kt*64;
        const bool active = (k0 <= q0 + m0 + 15);
        if (active) {
            const unsigned kS = sK + (kt&1)*KST*4;
            const unsigned vS = sV + (kt&1)*VST*4;

            float S[8][4];
#pragma unroll
            for (int j=0;j<8;j++)
#pragma unroll
                for (int t2=0;t2<4;t2++) S[j][t2]=0.f;

#pragma unroll
            for (int kk = 0; kk < 12; kk++) {
                unsigned a[4];
                ldsm4(a, qbase + kk*32);
#pragma unroll
                for (int p = 0; p < 4; p++) {
                    unsigned bq[4];
                    ldsm4(bq, kS + ((p*16 + ln15)*QS)*4 + hi16 + kk*32);
                    unsigned b0[2] = {bq[0], bq[2]};
                    unsigned b1[2] = {bq[1], bq[3]};
                    mma_h16(S[p*2  ], a, b0);
                    mma_h16(S[p*2+1], a, b1);
                }
            }

            if (k0 + 63 > q0 + m0) {
                const int row0 = q0 + m0 + r;
                const int row1 = row0 + 8;
#pragma unroll
                for (int j = 0; j < 8; j++) {
                    int col = k0 + j*8 + 2*c;
                    if (col   > row0) S[j][0] = -1e30f;
                    if (col+1 > row0) S[j][1] = -1e30f;
                    if (col   > row1) S[j][2] = -1e30f;
                    if (col+1 > row1) S[j][3] = -1e30f;
                }
            }

            float mx0 = -1e30f, mx1 = -1e30f;
#pragma unroll
            for (int j=0;j<8;j++) {
                mx0 = fmaxf(mx0, fmaxf(S[j][0], S[j][1]));
                mx1 = fmaxf(mx1, fmaxf(S[j][2], S[j][3]));
            }
            mx0 = fmaxf(mx0, __shfl_xor_sync(0xffffffffu, mx0, 1));
            mx0 = fmaxf(mx0, __shfl_xor_sync(0xffffffffu, mx0, 2));
            mx1 = fmaxf(mx1, __shfl_xor_sync(0xffffffffu, mx1, 1));
            mx1 = fmaxf(mx1, __shfl_xor_sync(0xffffffffu, mx1, 2));

            float mn0 = fmaxf(m_i[0], mx0), mn1 = fmaxf(m_i[1], mx1);
            float corr0 = __expf(m_i[0]-mn0), corr1 = __expf(m_i[1]-mn1);
            float rs0 = 0.f, rs1 = 0.f;
#pragma unroll
            for (int j=0;j<8;j++) {
                S[j][0] = __expf(S[j][0]-mn0); rs0 += S[j][0];
                S[j][1] = __expf(S[j][1]-mn0); rs0 += S[j][1];
                S[j][2] = __expf(S[j][2]-mn1); rs1 += S[j][2];
                S[j][3] = __expf(S[j][3]-mn1); rs1 += S[j][3];
            }
            rs0 += __shfl_xor_sync(0xffffffffu, rs0, 1);
            rs0 += __shfl_xor_sync(0xffffffffu, rs0, 2);
            rs1 += __shfl_xor_sync(0xffffffffu, rs1, 1);
            rs1 += __shfl_xor_sync(0xffffffffu, rs1, 2);
            l_i[0] = l_i[0]*corr0 + rs0;  m_i[0] = mn0;
            l_i[1] = l_i[1]*corr1 + rs1;  m_i[1] = mn1;

#pragma unroll
            for (int nb=0; nb<16; nb++) {
                O[nb][0]*=corr0; O[nb][1]*=corr0;
                O[nb][2]*=corr1; O[nb][3]*=corr1;
            }

#pragma unroll
            for (int kk = 0; kk < 4; kk++) {
                unsigned pa[4];
                {
                    __half2 h0 = __floats2half2_rn(S[2*kk  ][0], S[2*kk  ][1]);
                    __half2 h1 = __floats2half2_rn(S[2*kk  ][2], S[2*kk  ][3]);
                    __half2 h2 = __floats2half2_rn(S[2*kk+1][0], S[2*kk+1][1]);
                    __half2 h3 = __floats2half2_rn(S[2*kk+1][2], S[2*kk+1][3]);
                    pa[0] = *(unsigned*)&h0;
                    pa[1] = *(unsigned*)&h1;
                    pa[2] = *(unsigned*)&h2;
                    pa[3] = *(unsigned*)&h3;
                }
#pragma unroll
                for (int p = 0; p < 8; p++) {
                    unsigned bq[4];
                    ldsm4(bq, vS + ((p*16 + ln15)*VS)*4 + hi16 + kk*32);
                    unsigned b0[2] = {bq[0], bq[2]};
                    unsigned b1[2] = {bq[1], bq[3]};
                    mma_h16(O[p*2  ], pa, b0);
                    mma_h16(O[p*2+1], pa, b1);
                }
            }
        }
    }

    const int b = bh >> 4, h = bh & 15;
    const float inv0 = 1.0f / l_i[0];
    const float inv1 = 1.0f / l_i[1];
    const int l0 = q0 + m0 + r;
    __half* d0 = g_ao + ((size_t)(b*Ll + l0    ))*Dd + h*DHh;
    __half* d1 = g_ao + ((size_t)(b*Ll + l0 + 8))*Dd + h*DHh;
#pragma unroll
    for (int nb=0; nb<16; nb++) {
        *(__half2*)&d0[nb*8 + 2*c] = __floats2half2_rn(O[nb][0]*inv0, O[nb][1]*inv0);
        *(__half2*)&d1[nb*8 + 2*c] = __floats2half2_rn(O[nb][2]*inv1, O[nb][3]*inv1);
    }
}

// ---------------- launch ----------------
extern "C" void kernel_launch(void* const* d_in, const int* in_sizes, int n_in,
                              void* d_out, int out_size)
{
    const float* x     = (const float*)d_in[0];
    const float* W_DKV = (const float*)d_in[1];
    const float* W_UK  = (const float*)d_in[2];
    const float* W_UV  = (const float*)d_in[3];
    const float* W_DQ  = (const float*)d_in[4];
    const float* W_UQ  = (const float*)d_in[5];
    const float* W_QR  = (const float*)d_in[6];
    const float* W_KR  = (const float*)d_in[7];
    const float* W_O   = (const float*)d_in[8];
    const float* s_qk  = (const float*)d_in[9];
    float* out = (float*)d_out;

    __half *xh, *w1t, *w2t, *w3t, *woT, *c1, *c2, *c3, *ao;
    cudaGetSymbolAddress((void**)&xh,  g_xh);
    cudaGetSymbolAddress((void**)&w1t, g_w1t);
    cudaGetSymbolAddress((void**)&w2t, g_w2t);
    cudaGetSymbolAddress((void**)&w3t, g_w3t);
    cudaGetSymbolAddress((void**)&woT, g_woT);
    cudaGetSymbolAddress((void**)&c1,  g_c1);
    cudaGetSymbolAddress((void**)&c2,  g_c2);
    cudaGetSymbolAddress((void**)&c3,  g_c3);
    cudaGetSymbolAddress((void**)&ao,  g_ao);

    const int gemm_smem = 6*GST*4;                              // 110592
    cudaFuncSetAttribute(h16_gemm<false>, cudaFuncAttributeMaxDynamicSharedMemorySize, gemm_smem);
    cudaFuncSetAttribute(h16_gemm<true>,  cudaFuncAttributeMaxDynamicSharedMemorySize, gemm_smem);
    cudaFuncSetAttribute(h16_gemm23,      cudaFuncAttributeMaxDynamicSharedMemorySize, gemm_smem);
    const int attn_smem = (BQA*QS + 2*KST + 2*VST) * 4;         // 190464
    cudaFuncSetAttribute(attn_h16, cudaFuncAttributeMaxDynamicSharedMemorySize, attn_smem);

    dim3 thr(256);

    // 1: fused pre-pass
    fused_pre<<<PRE_NBLK, thr>>>(x, W_DKV, W_DQ, W_KR, W_UK, W_UV, W_UQ, W_QR, W_O);

    // 2: g1: x -> [ckv | cq | kr]
    h16_gemm<false><<<dim3((N1+127)/128, Mtok/128), thr, gemm_smem>>>(xh, w1t, c1, N1, Dd, Dd, N1);

    // 3: fused g2+g3 (independent, one wave-tail)
    h16_gemm23<<<dim3(N2/128 + N3/128, Mtok/128), thr, gemm_smem>>>(c1, w2t, w3t, c2, c3);

    // 4: prep (warp-per-token-head) + V transpose
    prep4<<<PREP_WBLK + 2048, thr>>>(s_qk);

    // 5: attention
    attn_h16<<<dim3(Ll/BQA, Bb*NHh), 512, attn_smem>>>();

    // 6: output projection -> d_out
    h16_gemm<true><<<dim3(Dd/128, Mtok/128), thr, gemm_smem>>>(ao, woT, out, Dd, Dd, Dd, Dd);
}

// round 15
// speedup vs baseline: 1.1203x; 1.0141x over previous
#include <cuda_runtime.h>
#include <cuda_fp16.h>
#include <math.h>

// ---------------- problem constants ----------------
#define Bb 4
#define Ll 2048
#define Dd 2048
#define NHh 16
#define DHh 128
#define DHRr 64
#define DCc 1024
#define Mtok (Bb*Ll)            // 8192
#define QKD 192                 // DH + DHR
#define N1 (DCc + DCc + DHRr)   // 2112 : [ckv | cq | kr]
#define N2 (Dd + Dd)            // 4096 : [kc | vfl]
#define N3 (Dd + NHh*DHRr)      // 3072 : [qc | qr]

// ---------------- device scratch (static, allocation-free) ----------------
__device__ __half g_xh  [(size_t)Mtok*Dd];
__device__ __half g_w1t [(size_t)N1*Dd];
__device__ __half g_w2t [(size_t)N2*DCc];
__device__ __half g_w3t [(size_t)N3*DCc];
__device__ __half g_woT [(size_t)Dd*Dd];
__device__ __half g_c1  [(size_t)Mtok*N1];   // ckv | cq | kr
__device__ __half g_c2  [(size_t)Mtok*N2];   // kc | vfl
__device__ __half g_c3  [(size_t)Mtok*N3];   // qc | qr
__device__ __half g_q   [(size_t)Bb*NHh*Ll*QKD];
__device__ __half g_k   [(size_t)Bb*NHh*Ll*QKD];
__device__ __half g_vt  [(size_t)Bb*NHh*DHh*Ll];   // [bh][d][l]
__device__ __half g_ao  [(size_t)Mtok*Dd];
__device__ float  g_cs  [Ll*32];
__device__ float  g_sn  [Ll*32];

// ---------------- asm helpers ----------------
__device__ __forceinline__ void mma_h16(float* d, const unsigned* a, const unsigned* b) {
    asm volatile(
        "mma.sync.aligned.m16n8k16.row.col.f32.f16.f16.f32 "
        "{%0,%1,%2,%3}, {%4,%5,%6,%7}, {%8,%9}, {%0,%1,%2,%3};"
        : "+f"(d[0]), "+f"(d[1]), "+f"(d[2]), "+f"(d[3])
        : "r"(a[0]), "r"(a[1]), "r"(a[2]), "r"(a[3]), "r"(b[0]), "r"(b[1]));
}

__device__ __forceinline__ unsigned smem_u32(const void* p) {
    return (unsigned)__cvta_generic_to_shared(p);
}

__device__ __forceinline__ void ldsm4(unsigned* r, unsigned addr) {
    asm volatile("ldmatrix.sync.aligned.m8n8.x4.shared.b16 {%0,%1,%2,%3}, [%4];"
        : "=r"(r[0]), "=r"(r[1]), "=r"(r[2]), "=r"(r[3]) : "r"(addr));
}

__device__ __forceinline__ void cp16(unsigned dst, const void* src) {
    asm volatile("cp.async.cg.shared.global [%0], [%1], 16;" :: "r"(dst), "l"(src));
}
#define CP_COMMIT() asm volatile("cp.async.commit_group;")
#define CP_WAIT(N)  asm volatile("cp.async.wait_group %0;" :: "n"(N))

// ---------------- shared transpose tile helper ----------------
__device__ __forceinline__ void wtrans_tile(const float* __restrict__ W, __half* __restrict__ Wt,
                                            int K, int N, int t, __half (*tsh)[33])
{
    const int tid = threadIdx.x;
    const int nx = N/32;
    const int n0 = (t % nx)*32, k0 = (t / nx)*32;
    const int tx = tid & 31, ty = tid >> 5;
#pragma unroll
    for (int i=0;i<4;i++)
        tsh[ty+i*8][tx] = __float2half(W[(size_t)(k0+ty+i*8)*N + n0+tx]);
    __syncthreads();
#pragma unroll
    for (int i=0;i<4;i++)
        Wt[(size_t)(n0+ty+i*8)*K + k0+tx] = tsh[tx][ty+i*8];
}

// ---------------- pre-pass: rope table + x->fp16 + w1t transposes ----------
#define PRE_ROPE 256
#define PRE_CVT  16384
#define PRE_NBLK (PRE_ROPE + PRE_CVT + 4224)     // 20864
__global__ void __launch_bounds__(256) fused_pre(
    const float* __restrict__ x,
    const float* __restrict__ WDKV, const float* __restrict__ WDQ,
    const float* __restrict__ WKR)
{
    __shared__ __half tsh[32][33];
    int bid = blockIdx.x;
    const int tid = threadIdx.x;

    if (bid < PRE_ROPE) {
        int idx = bid*256 + tid;
        int l = idx >> 5, jj = idx & 31;
        float inv = powf(10000.0f, -(float)jj/32.0f);
        float ang = (float)l * inv;
        g_cs[l*32 + jj] = cosf(ang);
        g_sn[l*32 + jj] = sinf(ang);
        return;
    }
    bid -= PRE_ROPE;
    if (bid < PRE_CVT) {
        int i = bid*256 + tid;
        float4 v = ((const float4*)x)[i];
        __half2* o = (__half2*)g_xh;
        o[2*i]   = __floats2half2_rn(v.x, v.y);
        o[2*i+1] = __floats2half2_rn(v.z, v.w);
        return;
    }
    bid -= PRE_CVT;

    if      (bid < 2048) wtrans_tile(WDKV, g_w1t,                  Dd, DCc,  bid,      tsh);
    else if (bid < 4096) wtrans_tile(WDQ,  g_w1t+(size_t)DCc*Dd,   Dd, DCc,  bid-2048, tsh);
    else                 wtrans_tile(WKR,  g_w1t+(size_t)2*DCc*Dd, Dd, DHRr, bid-4096, tsh);
}

// ---------------- fp16 tensor-core GEMM body ----------------
#define SW 36
#define GST (128*SW)
template<bool OUTF32>
__device__ __forceinline__ void gemm_body(
    const __half* __restrict__ A, const __half* __restrict__ Bt,
    void* __restrict__ Cv, int N, int K, int lda, int ldc,
    int bx, int by, unsigned sA)
{
    const unsigned sB = sA + 3*GST*4;

    const int tid  = threadIdx.x;
    const int lane = tid & 31;
    const int warp = tid >> 5;
    const int wm = warp >> 2, wn = warp & 3;
    const int ln15 = lane & 15;
    const int hi16 = (lane >> 4) * 16;

    const __half* Ag = A  + (size_t)by * 128 * lda;
    const __half* Bg = Bt + (size_t)bx * 128 * K;
    const int nrem = N - bx*128;

    unsigned afo[4], bfo[2];
#pragma unroll
    for (int ma=0; ma<4; ma++) afo[ma] = ((wm*64 + ma*16 + ln15)*SW)*4 + hi16;
#pragma unroll
    for (int nb=0; nb<2; nb++) bfo[nb] = ((wn*32 + nb*16 + ln15)*SW)*4 + hi16;

    float acc[4][4][4];
#pragma unroll
    for (int i=0;i<4;i++)
#pragma unroll
        for (int j=0;j<4;j++)
#pragma unroll
            for (int t=0;t<4;t++) acc[i][j][t]=0.f;

    const int nk = K/64;

    auto fill = [&](int s, int k0) {
        const unsigned aB = sA + s*GST*4;
        const unsigned bB = sB + s*GST*4;
#pragma unroll
        for (int i = 0; i < 4; i++) {
            int idx = tid + i*256;
            int row = idx >> 3, ch = idx & 7;
            cp16(aB + row*SW*4 + ch*16, Ag + (size_t)row*lda + k0 + ch*8);
        }
#pragma unroll
        for (int i = 0; i < 4; i++) {
            int idx = tid + i*256;
            int row = idx >> 3, ch = idx & 7;
            int gr = (row < nrem) ? row : (nrem-1);
            cp16(bB + row*SW*4 + ch*16, Bg + (size_t)gr*K + k0 + ch*8);
        }
    };

    fill(0, 0);  CP_COMMIT();
    fill(1, 64); CP_COMMIT();

    for (int kt=0; kt<nk; kt++) {
        CP_WAIT(1);
        __syncthreads();

        const int kn = kt+2;
        if (kn < nk) fill(kn % 3, kn*64);
        CP_COMMIT();

        const unsigned aS = sA + (kt%3)*GST*4;
        const unsigned bS = sB + (kt%3)*GST*4;
#pragma unroll
        for (int kc8 = 0; kc8 < 32; kc8 += 8) {
            unsigned af[4][4];
#pragma unroll
            for (int ma=0;ma<4;ma++)
                ldsm4(af[ma], aS + afo[ma] + kc8*4);
#pragma unroll
            for (int nb=0;nb<2;nb++) {
                unsigned bq[4];
                ldsm4(bq, bS + bfo[nb] + kc8*4);
                unsigned b0[2] = {bq[0], bq[2]};
                unsigned b1[2] = {bq[1], bq[3]};
#pragma unroll
                for (int ma=0;ma<4;ma++) {
                    mma_h16(acc[ma][nb*2  ], af[ma], b0);
                    mma_h16(acc[ma][nb*2+1], af[ma], b1);
                }
            }
        }
    }

    const int r = lane >> 2, c = lane & 3;
#pragma unroll
    for (int ma=0;ma<4;ma++) {
        int m = by*128 + wm*64 + ma*16 + r;
#pragma unroll
        for (int na=0;na<4;na++) {
            int n = bx*128 + wn*32 + na*8 + 2*c;
            if (n < N) {
                if (OUTF32) {
                    float* C = (float*)Cv;
                    *(float2*)&C[(size_t)m*ldc + n]     = make_float2(acc[ma][na][0], acc[ma][na][1]);
                    *(float2*)&C[(size_t)(m+8)*ldc + n] = make_float2(acc[ma][na][2], acc[ma][na][3]);
                } else {
                    __half* C = (__half*)Cv;
                    *(__half2*)&C[(size_t)m*ldc + n]     = __floats2half2_rn(acc[ma][na][0], acc[ma][na][1]);
                    *(__half2*)&C[(size_t)(m+8)*ldc + n] = __floats2half2_rn(acc[ma][na][2], acc[ma][na][3]);
                }
            }
        }
    }
}

template<bool OUTF32>
__global__ void __launch_bounds__(256, 2)
h16_gemm(const __half* __restrict__ A, const __half* __restrict__ Bt,
         void* __restrict__ Cv, int N, int K, int lda, int ldc)
{
    extern __shared__ unsigned gsm[];
    gemm_body<OUTF32>(A, Bt, Cv, N, K, lda, ldc, blockIdx.x, blockIdx.y, smem_u32(gsm));
}

// g1 fused with w2t/w3t/woT transposes (independent memory work rides along).
// 1D grid: [0, 17*64) gemm g1; then 11264 transpose tiles.
#define G1_BX ((N1+127)/128)         // 17
#define G1_GEMM (G1_BX*(Mtok/128))   // 1088
#define G1_NBLK (G1_GEMM + 2048+2048+2048+1024+4096)  // 12352
__global__ void __launch_bounds__(256, 2)
h16_gemm1x(const __half* __restrict__ xh, const __half* __restrict__ w1t,
           __half* __restrict__ c1,
           const float* __restrict__ WUK, const float* __restrict__ WUV,
           const float* __restrict__ WUQ, const float* __restrict__ WQR,
           const float* __restrict__ WO)
{
    extern __shared__ unsigned gsm[];
    int bid = blockIdx.x;
    if (bid < G1_GEMM) {
        gemm_body<false>(xh, w1t, c1, N1, Dd, Dd, N1,
                         bid % G1_BX, bid / G1_BX, smem_u32(gsm));
        return;
    }
    bid -= G1_GEMM;
    __half (*tsh)[33] = (__half(*)[33])gsm;
    if      (bid <  2048) wtrans_tile(WUK, g_w2t,                 DCc, Dd,       bid,       tsh);
    else if (bid <  4096) wtrans_tile(WUV, g_w2t+(size_t)Dd*DCc,  DCc, Dd,       bid-2048,  tsh);
    else if (bid <  6144) wtrans_tile(WUQ, g_w3t,                 DCc, Dd,       bid-4096,  tsh);
    else if (bid <  7168) wtrans_tile(WQR, g_w3t+(size_t)Dd*DCc,  DCc, NHh*DHRr, bid-6144,  tsh);
    else                  wtrans_tile(WO,  g_woT,                 Dd,  Dd,       bid-7168,  tsh);
}

// fused g2+g3
__global__ void __launch_bounds__(256, 2)
h16_gemm23(const __half* __restrict__ c1, const __half* __restrict__ w2t,
           const __half* __restrict__ w3t, __half* __restrict__ c2,
           __half* __restrict__ c3)
{
    extern __shared__ unsigned gsm[];
    const int bx = blockIdx.x;
    if (bx < N2/128)
        gemm_body<false>(c1, w2t, c2, N2, DCc, N1, N2, bx, blockIdx.y, smem_u32(gsm));
    else
        gemm_body<false>(c1 + DCc, w3t, c3, N3, DCc, N1, N3, bx - N2/128, blockIdx.y, smem_u32(gsm));
}

// ---------------- prep4: warp-per-(token,head), half2-vectorized; + vtrans -
#define PREP_WBLK (Mtok*NHh/8)     // 16384
__global__ void __launch_bounds__(256) prep4(const float* __restrict__ s_qk_ptr)
{
    __shared__ __half tv[64][DHh+8];
    int bid = blockIdx.x;
    const int tid = threadIdx.x;

    if (bid < PREP_WBLK) {
        const int lane = tid & 31, warp = tid >> 5;
        const int id = bid*8 + warp;
        const int bl = id & (Mtok-1);
        const int h  = id >> 13;
        const int b = bl >> 11, l = bl & 2047;
        const float s_qk = *s_qk_ptr;

        // lane owns elements (2*lane, 2*lane+1) within each of 3 groups of 64
        float kv[6], qv[6];
#pragma unroll
        for (int g=0; g<2; g++) {
            int t = g*64 + 2*lane;
            __half2 kh = *(const __half2*)&g_c2[(size_t)bl*N2 + h*DHh + t];
            __half2 qh = *(const __half2*)&g_c3[(size_t)bl*N3 + h*DHh + t];
            float2 kf = __half22float2(kh), qf = __half22float2(qh);
            kv[2*g] = kf.x; kv[2*g+1] = kf.y;
            qv[2*g] = qf.x; qv[2*g+1] = qf.y;
        }
        {
            int j = 2*lane;                 // 0..62 even; j,j+1 same half
            int jj = j & 31;                // even
            float2 cs2 = *(const float2*)&g_cs[l*32 + jj];
            float2 sn2 = *(const float2*)&g_sn[l*32 + jj];
            const __half* krp = g_c1 + (size_t)bl*N1 + 2*DCc;
            const __half* qrp = g_c3 + (size_t)bl*N3 + Dd + h*DHRr;
            float2 kj = __half22float2(*(const __half2*)&krp[j]);
            float2 ko = __half22float2(*(const __half2*)&krp[j^32]);
            float2 qj = __half22float2(*(const __half2*)&qrp[j]);
            float2 qo = __half22float2(*(const __half2*)&qrp[j^32]);
            float sgn = (j < 32) ? -1.f : 1.f;
            kv[4] = kj.x*cs2.x + sgn*ko.x*sn2.x;
            kv[5] = kj.y*cs2.y + sgn*ko.y*sn2.y;
            qv[4] = qj.x*cs2.x + sgn*qo.x*sn2.x;
            qv[5] = qj.y*cs2.y + sgn*qo.y*sn2.y;
        }

        float ks = 0.f, qs = 0.f;
#pragma unroll
        for (int i=0;i<6;i++) { ks += kv[i]*kv[i]; qs += qv[i]*qv[i]; }
#pragma unroll
        for (int o=16;o>0;o>>=1) {
            ks += __shfl_xor_sync(0xffffffffu, ks, o);
            qs += __shfl_xor_sync(0xffffffffu, qs, o);
        }
        float invk = 1.0f / fmaxf(sqrtf(ks), 1e-12f);
        float invq = s_qk / fmaxf(sqrtf(qs), 1e-12f);

        size_t off = ((size_t)(b*NHh + h)*Ll + l)*QKD;
#pragma unroll
        for (int g=0; g<3; g++) {
            int t = g*64 + 2*lane;
            *(__half2*)&g_k[off + t] = __floats2half2_rn(kv[2*g]*invk, kv[2*g+1]*invk);
            *(__half2*)&g_q[off + t] = __floats2half2_rn(qv[2*g]*invq, qv[2*g+1]*invq);
        }
        return;
    }

    // ---- vtrans region ----
    const int vb = bid - PREP_WBLK;
    const int bh = vb >> 5, lxb = vb & 31;
    const int b = bh >> 4, h = bh & 15;
    const int l0 = lxb * 64;

    for (int i = tid; i < 64*16; i += 256) {
        int l = i >> 4, ch = i & 15;
        *(uint4*)&tv[l][ch*8] =
            *(const uint4*)(g_c2 + ((size_t)(b*Ll + l0 + l))*N2 + Dd + h*DHh + ch*8);
    }
    __syncthreads();
    for (int i = tid; i < 128*8; i += 256) {
        int d = i >> 3, ch = i & 7;
        __half2 p[4];
#pragma unroll
        for (int u=0;u<4;u++) {
            int l = ch*8 + u*2;
            p[u] = __halves2half2(tv[l][d], tv[l+1][d]);
        }
        *(uint4*)(g_vt + (size_t)bh*DHh*Ll + (size_t)d*Ll + l0 + ch*8) = *(uint4*)p;
    }
}

// ---------------- fp16 flash attention (causal, BQ=256, BK=64) -------------
#define QS 100
#define VS 36
#define KST (64*QS)
#define VST (128*VS)
#define BQA 256
__global__ void __launch_bounds__(512, 1) attn_h16()
{
    extern __shared__ unsigned smu[];
    const unsigned sQ = smem_u32(smu);          // [256][100]
    const unsigned sK = sQ + BQA*QS*4;          // 2 stages [64][100]
    const unsigned sV = sK + 2*KST*4;           // 2 stages [128][36]

    const int qt = (gridDim.x - 1) - blockIdx.x;
    const int bh = blockIdx.y;
    const int q0 = qt * BQA;
    const __half* Qg = g_q  + (size_t)bh*Ll*QKD + (size_t)q0*QKD;
    const __half* Kg = g_k  + (size_t)bh*Ll*QKD;
    const __half* Vg = g_vt + (size_t)bh*DHh*Ll;

    const int tid  = threadIdx.x;
    const int lane = tid & 31;
    const int warp = tid >> 5;
    const int r = lane >> 2, c = lane & 3;
    const int ln15 = lane & 15;
    const int hi16 = (lane >> 4) * 16;
    const int m0 = warp * 16;

    auto fillKV = [&](int s, int k0) {
        const unsigned kS = sK + s*KST*4;
        const unsigned vS = sV + s*VST*4;
        for (int i = tid; i < 64*24; i += 512) {
            int row = i / 24, ch = i % 24;
            cp16(kS + (row*QS + ch*4)*4, Kg + (size_t)(k0+row)*QKD + ch*8);
        }
        for (int i = tid; i < 128*8; i += 512) {
            int d = i >> 3, ch = i & 7;
            cp16(vS + (d*VS + ch*4)*4, Vg + (size_t)d*Ll + k0 + ch*8);
        }
    };

    for (int i = tid; i < BQA*24; i += 512) {
        int row = i / 24, ch = i % 24;
        *(uint4*)&smu[row*QS + ch*4] = *(const uint4*)(Qg + (size_t)row*QKD + ch*8);
    }
    fillKV(0, 0);
    CP_COMMIT();

    const unsigned qbase = sQ + ((m0 + ln15)*QS)*4 + hi16;

    float O[16][4];
#pragma unroll
    for (int nb=0; nb<16; nb++)
#pragma unroll
        for (int t2=0; t2<4; t2++) O[nb][t2] = 0.f;
    float m_i[2] = {-1e30f, -1e30f};
    float l_i[2] = {0.f, 0.f};

    const int nkt = 4*(qt+1);

    for (int kt = 0; kt < nkt; kt++) {
        CP_WAIT(0);
        __syncthreads();
        if (kt+1 < nkt) fillKV((kt+1)&1, (kt+1)*64);
        CP_COMMIT();

        const int k0 = kt*64;
        const bool active = (k0 <= q0 + m0 + 15);
        if (active) {
            const unsigned kS = sK + (kt&1)*KST*4;
            const unsigned vS = sV + (kt&1)*VST*4;

            float S[8][4];
#pragma unroll
            for (int j=0;j<8;j++)
#pragma unroll
                for (int t2=0;t2<4;t2++) S[j][t2]=0.f;

#pragma unroll
            for (int kk = 0; kk < 12; kk++) {
                unsigned a[4];
                ldsm4(a, qbase + kk*32);
#pragma unroll
                for (int p = 0; p < 4; p++) {
                    unsigned bq[4];
                    ldsm4(bq, kS + ((p*16 + ln15)*QS)*4 + hi16 + kk*32);
                    unsigned b0[2] = {bq[0], bq[2]};
                    unsigned b1[2] = {bq[1], bq[3]};
                    mma_h16(S[p*2  ], a, b0);
                    mma_h16(S[p*2+1], a, b1);
                }
            }

            if (k0 + 63 > q0 + m0) {
                const int row0 = q0 + m0 + r;
                const int row1 = row0 + 8;
#pragma unroll
                for (int j = 0; j < 8; j++) {
                    int col = k0 + j*8 + 2*c;
                    if (col   > row0) S[j][0] = -1e30f;
                    if (col+1 > row0) S[j][1] = -1e30f;
                    if (col   > row1) S[j][2] = -1e30f;
                    if (col+1 > row1) S[j][3] = -1e30f;
                }
            }

            float mx0 = -1e30f, mx1 = -1e30f;
#pragma unroll
            for (int j=0;j<8;j++) {
                mx0 = fmaxf(mx0, fmaxf(S[j][0], S[j][1]));
                mx1 = fmaxf(mx1, fmaxf(S[j][2], S[j][3]));
            }
            mx0 = fmaxf(mx0, __shfl_xor_sync(0xffffffffu, mx0, 1));
            mx0 = fmaxf(mx0, __shfl_xor_sync(0xffffffffu, mx0, 2));
            mx1 = fmaxf(mx1, __shfl_xor_sync(0xffffffffu, mx1, 1));
            mx1 = fmaxf(mx1, __shfl_xor_sync(0xffffffffu, mx1, 2));

            float mn0 = fmaxf(m_i[0], mx0), mn1 = fmaxf(m_i[1], mx1);
            float corr0 = __expf(m_i[0]-mn0), corr1 = __expf(m_i[1]-mn1);
            float rs0 = 0.f, rs1 = 0.f;
#pragma unroll
            for (int j=0;j<8;j++) {
                S[j][0] = __expf(S[j][0]-mn0); rs0 += S[j][0];
                S[j][1] = __expf(S[j][1]-mn0); rs0 += S[j][1];
                S[j][2] = __expf(S[j][2]-mn1); rs1 += S[j][2];
                S[j][3] = __expf(S[j][3]-mn1); rs1 += S[j][3];
            }
            rs0 += __shfl_xor_sync(0xffffffffu, rs0, 1);
            rs0 += __shfl_xor_sync(0xffffffffu, rs0, 2);
            rs1 += __shfl_xor_sync(0xffffffffu, rs1, 1);
            rs1 += __shfl_xor_sync(0xffffffffu, rs1, 2);
            l_i[0] = l_i[0]*corr0 + rs0;  m_i[0] = mn0;
            l_i[1] = l_i[1]*corr1 + rs1;  m_i[1] = mn1;

#pragma unroll
            for (int nb=0; nb<16; nb++) {
                O[nb][0]*=corr0; O[nb][1]*=corr0;
                O[nb][2]*=corr1; O[nb][3]*=corr1;
            }

#pragma unroll
            for (int kk = 0; kk < 4; kk++) {
                unsigned pa[4];
                {
                    __half2 h0 = __floats2half2_rn(S[2*kk  ][0], S[2*kk  ][1]);
                    __half2 h1 = __floats2half2_rn(S[2*kk  ][2], S[2*kk  ][3]);
                    __half2 h2 = __floats2half2_rn(S[2*kk+1][0], S[2*kk+1][1]);
                    __half2 h3 = __floats2half2_rn(S[2*kk+1][2], S[2*kk+1][3]);
                    pa[0] = *(unsigned*)&h0;
                    pa[1] = *(unsigned*)&h1;
                    pa[2] = *(unsigned*)&h2;
                    pa[3] = *(unsigned*)&h3;
                }
#pragma unroll
                for (int p = 0; p < 8; p++) {
                    unsigned bq[4];
                    ldsm4(bq, vS + ((p*16 + ln15)*VS)*4 + hi16 + kk*32);
                    unsigned b0[2] = {bq[0], bq[2]};
                    unsigned b1[2] = {bq[1], bq[3]};
                    mma_h16(O[p*2  ], pa, b0);
                    mma_h16(O[p*2+1], pa, b1);
                }
            }
        }
    }

    const int b = bh >> 4, h = bh & 15;
    const float inv0 = 1.0f / l_i[0];
    const float inv1 = 1.0f / l_i[1];
    const int l0 = q0 + m0 + r;
    __half* d0 = g_ao + ((size_t)(b*Ll + l0    ))*Dd + h*DHh;
    __half* d1 = g_ao + ((size_t)(b*Ll + l0 + 8))*Dd + h*DHh;
#pragma unroll
    for (int nb=0; nb<16; nb++) {
        *(__half2*)&d0[nb*8 + 2*c] = __floats2half2_rn(O[nb][0]*inv0, O[nb][1]*inv0);
        *(__half2*)&d1[nb*8 + 2*c] = __floats2half2_rn(O[nb][2]*inv1, O[nb][3]*inv1);
    }
}

// ---------------- launch ----------------
extern "C" void kernel_launch(void* const* d_in, const int* in_sizes, int n_in,
                              void* d_out, int out_size)
{
    const float* x     = (const float*)d_in[0];
    const float* W_DKV = (const float*)d_in[1];
    const float* W_UK  = (const float*)d_in[2];
    const float* W_UV  = (const float*)d_in[3];
    const float* W_DQ  = (const float*)d_in[4];
    const float* W_UQ  = (const float*)d_in[5];
    const float* W_QR  = (const float*)d_in[6];
    const float* W_KR  = (const float*)d_in[7];
    const float* W_O   = (const float*)d_in[8];
    const float* s_qk  = (const float*)d_in[9];
    float* out = (float*)d_out;

    __half *xh, *w1t, *w2t, *w3t, *woT, *c1, *c2, *c3, *ao;
    cudaGetSymbolAddress((void**)&xh,  g_xh);
    cudaGetSymbolAddress((void**)&w1t, g_w1t);
    cudaGetSymbolAddress((void**)&w2t, g_w2t);
    cudaGetSymbolAddress((void**)&w3t, g_w3t);
    cudaGetSymbolAddress((void**)&woT, g_woT);
    cudaGetSymbolAddress((void**)&c1,  g_c1);
    cudaGetSymbolAddress((void**)&c2,  g_c2);
    cudaGetSymbolAddress((void**)&c3,  g_c3);
    cudaGetSymbolAddress((void**)&ao,  g_ao);

    const int gemm_smem = 6*GST*4;                              // 110592
    cudaFuncSetAttribute(h16_gemm<false>, cudaFuncAttributeMaxDynamicSharedMemorySize, gemm_smem);
    cudaFuncSetAttribute(h16_gemm<true>,  cudaFuncAttributeMaxDynamicSharedMemorySize, gemm_smem);
    cudaFuncSetAttribute(h16_gemm1x,      cudaFuncAttributeMaxDynamicSharedMemorySize, gemm_smem);
    cudaFuncSetAttribute(h16_gemm23,      cudaFuncAttributeMaxDynamicSharedMemorySize, gemm_smem);
    const int attn_smem = (BQA*QS + 2*KST + 2*VST) * 4;         // 190464
    cudaFuncSetAttribute(attn_h16, cudaFuncAttributeMaxDynamicSharedMemorySize, attn_smem);

    dim3 thr(256);

    // 1: pre (rope + cvt_x + w1t transposes only)
    fused_pre<<<PRE_NBLK, thr>>>(x, W_DKV, W_DQ, W_KR);

    // 2: g1 fused with w2t/w3t/woT transposes (memory work overlaps compute)
    h16_gemm1x<<<G1_NBLK, thr, gemm_smem>>>(xh, w1t, c1, W_UK, W_UV, W_UQ, W_QR, W_O);

    // 3: fused g2+g3
    h16_gemm23<<<dim3(N2/128 + N3/128, Mtok/128), thr, gemm_smem>>>(c1, w2t, w3t, c2, c3);

    // 4: prep (half2-vectorized) + V transpose
    prep4<<<PREP_WBLK + 2048, thr>>>(s_qk);

    // 5: attention
    attn_h16<<<dim3(Ll/BQA, Bb*NHh), 512, attn_smem>>>();

    // 6: output projection -> d_out
    h16_gemm<true><<<dim3(Dd/128, Mtok/128), thr, gemm_smem>>>(ao, woT, out, Dd, Dd, Dd, Dd);
}

// round 16
// speedup vs baseline: 1.1461x; 1.0230x over previous
#include <cuda_runtime.h>
#include <cuda_fp16.h>
#include <math.h>

// ---------------- problem constants ----------------
#define Bb 4
#define Ll 2048
#define Dd 2048
#define NHh 16
#define DHh 128
#define DHRr 64
#define DCc 1024
#define Mtok (Bb*Ll)            // 8192
#define QKD 192                 // DH + DHR
#define N1 (DCc + DCc + DHRr)   // 2112 : [ckv | cq | kr]
#define N2 (Dd + Dd)            // 4096 : [kc | vfl]
#define N3 (Dd + NHh*DHRr)      // 3072 : [qc | qr]

// ---------------- device scratch (static, allocation-free) ----------------
__device__ __half g_xh  [(size_t)Mtok*Dd];
__device__ __half g_w1t [(size_t)N1*Dd];
__device__ __half g_w2t [(size_t)N2*DCc];
__device__ __half g_w3t [(size_t)N3*DCc];
__device__ __half g_woT [(size_t)Dd*Dd];
__device__ __half g_c1  [(size_t)Mtok*N1];   // ckv | cq | kr
__device__ __half g_c2  [(size_t)Mtok*N2];   // kc | vfl
__device__ __half g_c3  [(size_t)Mtok*N3];   // qc | qr
__device__ __half g_q   [(size_t)Bb*NHh*Ll*QKD];
__device__ __half g_k   [(size_t)Bb*NHh*Ll*QKD];
__device__ __half g_vt  [(size_t)Bb*NHh*DHh*Ll];   // [bh][d][l]
__device__ __half g_ao  [(size_t)Mtok*Dd];
__device__ float  g_cs  [Ll*32];
__device__ float  g_sn  [Ll*32];

// ---------------- asm helpers ----------------
__device__ __forceinline__ void mma_h16(float* d, const unsigned* a, const unsigned* b) {
    asm volatile(
        "mma.sync.aligned.m16n8k16.row.col.f32.f16.f16.f32 "
        "{%0,%1,%2,%3}, {%4,%5,%6,%7}, {%8,%9}, {%0,%1,%2,%3};"
        : "+f"(d[0]), "+f"(d[1]), "+f"(d[2]), "+f"(d[3])
        : "r"(a[0]), "r"(a[1]), "r"(a[2]), "r"(a[3]), "r"(b[0]), "r"(b[1]));
}

__device__ __forceinline__ unsigned smem_u32(const void* p) {
    return (unsigned)__cvta_generic_to_shared(p);
}

__device__ __forceinline__ void ldsm4(unsigned* r, unsigned addr) {
    asm volatile("ldmatrix.sync.aligned.m8n8.x4.shared.b16 {%0,%1,%2,%3}, [%4];"
        : "=r"(r[0]), "=r"(r[1]), "=r"(r[2]), "=r"(r[3]) : "r"(addr));
}

__device__ __forceinline__ void cp16(unsigned dst, const void* src) {
    asm volatile("cp.async.cg.shared.global [%0], [%1], 16;" :: "r"(dst), "l"(src));
}
#define CP_COMMIT() asm volatile("cp.async.commit_group;")
#define CP_WAIT(N)  asm volatile("cp.async.wait_group %0;" :: "n"(N))

// ---------------- shared transpose tile helper ----------------
__device__ __forceinline__ void wtrans_tile(const float* __restrict__ W, __half* __restrict__ Wt,
                                            int K, int N, int t, __half (*tsh)[33])
{
    const int tid = threadIdx.x;
    const int nx = N/32;
    const int n0 = (t % nx)*32, k0 = (t / nx)*32;
    const int tx = tid & 31, ty = tid >> 5;
#pragma unroll
    for (int i=0;i<4;i++)
        tsh[ty+i*8][tx] = __float2half(W[(size_t)(k0+ty+i*8)*N + n0+tx]);
    __syncthreads();
#pragma unroll
    for (int i=0;i<4;i++)
        Wt[(size_t)(n0+ty+i*8)*K + k0+tx] = tsh[tx][ty+i*8];
}

// ---------------- pre-pass: rope table + x->fp16 + w1t transposes ----------
#define PRE_ROPE 256
#define PRE_CVT  16384
#define PRE_NBLK (PRE_ROPE + PRE_CVT + 4224)     // 20864
__global__ void __launch_bounds__(256) fused_pre(
    const float* __restrict__ x,
    const float* __restrict__ WDKV, const float* __restrict__ WDQ,
    const float* __restrict__ WKR)
{
    __shared__ __half tsh[32][33];
    int bid = blockIdx.x;
    const int tid = threadIdx.x;

    if (bid < PRE_ROPE) {
        int idx = bid*256 + tid;
        int l = idx >> 5, jj = idx & 31;
        float inv = powf(10000.0f, -(float)jj/32.0f);
        float ang = (float)l * inv;
        g_cs[l*32 + jj] = cosf(ang);
        g_sn[l*32 + jj] = sinf(ang);
        return;
    }
    bid -= PRE_ROPE;
    if (bid < PRE_CVT) {
        int i = bid*256 + tid;
        float4 v = ((const float4*)x)[i];
        __half2* o = (__half2*)g_xh;
        o[2*i]   = __floats2half2_rn(v.x, v.y);
        o[2*i+1] = __floats2half2_rn(v.z, v.w);
        return;
    }
    bid -= PRE_CVT;

    if      (bid < 2048) wtrans_tile(WDKV, g_w1t,                  Dd, DCc,  bid,      tsh);
    else if (bid < 4096) wtrans_tile(WDQ,  g_w1t+(size_t)DCc*Dd,   Dd, DCc,  bid-2048, tsh);
    else                 wtrans_tile(WKR,  g_w1t+(size_t)2*DCc*Dd, Dd, DHRr, bid-4096, tsh);
}

// ---------------- fp16 tensor-core GEMM body ----------------
#define SW 36
#define GST (128*SW)
template<bool OUTF32>
__device__ __forceinline__ void gemm_body(
    const __half* __restrict__ A, const __half* __restrict__ Bt,
    void* __restrict__ Cv, int N, int K, int lda, int ldc,
    int bx, int by, unsigned sA)
{
    const unsigned sB = sA + 3*GST*4;

    const int tid  = threadIdx.x;
    const int lane = tid & 31;
    const int warp = tid >> 5;
    const int wm = warp >> 2, wn = warp & 3;
    const int ln15 = lane & 15;
    const int hi16 = (lane >> 4) * 16;

    const __half* Ag = A  + (size_t)by * 128 * lda;
    const __half* Bg = Bt + (size_t)bx * 128 * K;
    const int nrem = N - bx*128;

    unsigned afo[4], bfo[2];
#pragma unroll
    for (int ma=0; ma<4; ma++) afo[ma] = ((wm*64 + ma*16 + ln15)*SW)*4 + hi16;
#pragma unroll
    for (int nb=0; nb<2; nb++) bfo[nb] = ((wn*32 + nb*16 + ln15)*SW)*4 + hi16;

    float acc[4][4][4];
#pragma unroll
    for (int i=0;i<4;i++)
#pragma unroll
        for (int j=0;j<4;j++)
#pragma unroll
            for (int t=0;t<4;t++) acc[i][j][t]=0.f;

    const int nk = K/64;

    auto fill = [&](int s, int k0) {
        const unsigned aB = sA + s*GST*4;
        const unsigned bB = sB + s*GST*4;
#pragma unroll
        for (int i = 0; i < 4; i++) {
            int idx = tid + i*256;
            int row = idx >> 3, ch = idx & 7;
            cp16(aB + row*SW*4 + ch*16, Ag + (size_t)row*lda + k0 + ch*8);
        }
#pragma unroll
        for (int i = 0; i < 4; i++) {
            int idx = tid + i*256;
            int row = idx >> 3, ch = idx & 7;
            int gr = (row < nrem) ? row : (nrem-1);
            cp16(bB + row*SW*4 + ch*16, Bg + (size_t)gr*K + k0 + ch*8);
        }
    };

    fill(0, 0);  CP_COMMIT();
    fill(1, 64); CP_COMMIT();

    for (int kt=0; kt<nk; kt++) {
        CP_WAIT(1);
        __syncthreads();

        const int kn = kt+2;
        if (kn < nk) fill(kn % 3, kn*64);
        CP_COMMIT();

        const unsigned aS = sA + (kt%3)*GST*4;
        const unsigned bS = sB + (kt%3)*GST*4;
#pragma unroll
        for (int kc8 = 0; kc8 < 32; kc8 += 8) {
            unsigned af[4][4];
#pragma unroll
            for (int ma=0;ma<4;ma++)
                ldsm4(af[ma], aS + afo[ma] + kc8*4);
#pragma unroll
            for (int nb=0;nb<2;nb++) {
                unsigned bq[4];
                ldsm4(bq, bS + bfo[nb] + kc8*4);
                unsigned b0[2] = {bq[0], bq[2]};
                unsigned b1[2] = {bq[1], bq[3]};
#pragma unroll
                for (int ma=0;ma<4;ma++) {
                    mma_h16(acc[ma][nb*2  ], af[ma], b0);
                    mma_h16(acc[ma][nb*2+1], af[ma], b1);
                }
            }
        }
    }

    const int r = lane >> 2, c = lane & 3;
#pragma unroll
    for (int ma=0;ma<4;ma++) {
        int m = by*128 + wm*64 + ma*16 + r;
#pragma unroll
        for (int na=0;na<4;na++) {
            int n = bx*128 + wn*32 + na*8 + 2*c;
            if (n < N) {
                if (OUTF32) {
                    float* C = (float*)Cv;
                    *(float2*)&C[(size_t)m*ldc + n]     = make_float2(acc[ma][na][0], acc[ma][na][1]);
                    *(float2*)&C[(size_t)(m+8)*ldc + n] = make_float2(acc[ma][na][2], acc[ma][na][3]);
                } else {
                    __half* C = (__half*)Cv;
                    *(__half2*)&C[(size_t)m*ldc + n]     = __floats2half2_rn(acc[ma][na][0], acc[ma][na][1]);
                    *(__half2*)&C[(size_t)(m+8)*ldc + n] = __floats2half2_rn(acc[ma][na][2], acc[ma][na][3]);
                }
            }
        }
    }
}

template<bool OUTF32>
__global__ void __launch_bounds__(256, 2)
h16_gemm(const __half* __restrict__ A, const __half* __restrict__ Bt,
         void* __restrict__ Cv, int N, int K, int lda, int ldc)
{
    extern __shared__ unsigned gsm[];
    gemm_body<OUTF32>(A, Bt, Cv, N, K, lda, ldc, blockIdx.x, blockIdx.y, smem_u32(gsm));
}

// g1 fused with w2t/w3t/woT transposes
#define G1_BX ((N1+127)/128)         // 17
#define G1_GEMM (G1_BX*(Mtok/128))   // 1088
#define G1_NBLK (G1_GEMM + 2048+2048+2048+1024+4096)  // 12352
__global__ void __launch_bounds__(256, 2)
h16_gemm1x(const __half* __restrict__ xh, const __half* __restrict__ w1t,
           __half* __restrict__ c1,
           const float* __restrict__ WUK, const float* __restrict__ WUV,
           const float* __restrict__ WUQ, const float* __restrict__ WQR,
           const float* __restrict__ WO)
{
    extern __shared__ unsigned gsm[];
    int bid = blockIdx.x;
    if (bid < G1_GEMM) {
        gemm_body<false>(xh, w1t, c1, N1, Dd, Dd, N1,
                         bid % G1_BX, bid / G1_BX, smem_u32(gsm));
        return;
    }
    bid -= G1_GEMM;
    __half (*tsh)[33] = (__half(*)[33])gsm;
    if      (bid <  2048) wtrans_tile(WUK, g_w2t,                 DCc, Dd,       bid,       tsh);
    else if (bid <  4096) wtrans_tile(WUV, g_w2t+(size_t)Dd*DCc,  DCc, Dd,       bid-2048,  tsh);
    else if (bid <  6144) wtrans_tile(WUQ, g_w3t,                 DCc, Dd,       bid-4096,  tsh);
    else if (bid <  7168) wtrans_tile(WQR, g_w3t+(size_t)Dd*DCc,  DCc, NHh*DHRr, bid-6144,  tsh);
    else                  wtrans_tile(WO,  g_woT,                 Dd,  Dd,       bid-7168,  tsh);
}

// fused g2+g3
__global__ void __launch_bounds__(256, 2)
h16_gemm23(const __half* __restrict__ c1, const __half* __restrict__ w2t,
           const __half* __restrict__ w3t, __half* __restrict__ c2,
           __half* __restrict__ c3)
{
    extern __shared__ unsigned gsm[];
    const int bx = blockIdx.x;
    if (bx < N2/128)
        gemm_body<false>(c1, w2t, c2, N2, DCc, N1, N2, bx, blockIdx.y, smem_u32(gsm));
    else
        gemm_body<false>(c1 + DCc, w3t, c3, N3, DCc, N1, N3, bx - N2/128, blockIdx.y, smem_u32(gsm));
}

// ---------------- prep4: warp-per-(token,head), half2-vectorized; + vtrans -
#define PREP_WBLK (Mtok*NHh/8)     // 16384
__global__ void __launch_bounds__(256) prep4(const float* __restrict__ s_qk_ptr)
{
    __shared__ __half tv[64][DHh+8];
    int bid = blockIdx.x;
    const int tid = threadIdx.x;

    if (bid < PREP_WBLK) {
        const int lane = tid & 31, warp = tid >> 5;
        const int id = bid*8 + warp;
        const int bl = id & (Mtok-1);
        const int h  = id >> 13;
        const int b = bl >> 11, l = bl & 2047;
        const float s_qk = *s_qk_ptr;

        float kv[6], qv[6];
#pragma unroll
        for (int g=0; g<2; g++) {
            int t = g*64 + 2*lane;
            __half2 kh = *(const __half2*)&g_c2[(size_t)bl*N2 + h*DHh + t];
            __half2 qh = *(const __half2*)&g_c3[(size_t)bl*N3 + h*DHh + t];
            float2 kf = __half22float2(kh), qf = __half22float2(qh);
            kv[2*g] = kf.x; kv[2*g+1] = kf.y;
            qv[2*g] = qf.x; qv[2*g+1] = qf.y;
        }
        {
            int j = 2*lane;
            int jj = j & 31;
            float2 cs2 = *(const float2*)&g_cs[l*32 + jj];
            float2 sn2 = *(const float2*)&g_sn[l*32 + jj];
            const __half* krp = g_c1 + (size_t)bl*N1 + 2*DCc;
            const __half* qrp = g_c3 + (size_t)bl*N3 + Dd + h*DHRr;
            float2 kj = __half22float2(*(const __half2*)&krp[j]);
            float2 ko = __half22float2(*(const __half2*)&krp[j^32]);
            float2 qj = __half22float2(*(const __half2*)&qrp[j]);
            float2 qo = __half22float2(*(const __half2*)&qrp[j^32]);
            float sgn = (j < 32) ? -1.f : 1.f;
            kv[4] = kj.x*cs2.x + sgn*ko.x*sn2.x;
            kv[5] = kj.y*cs2.y + sgn*ko.y*sn2.y;
            qv[4] = qj.x*cs2.x + sgn*qo.x*sn2.x;
            qv[5] = qj.y*cs2.y + sgn*qo.y*sn2.y;
        }

        float ks = 0.f, qs = 0.f;
#pragma unroll
        for (int i=0;i<6;i++) { ks += kv[i]*kv[i]; qs += qv[i]*qv[i]; }
#pragma unroll
        for (int o=16;o>0;o>>=1) {
            ks += __shfl_xor_sync(0xffffffffu, ks, o);
            qs += __shfl_xor_sync(0xffffffffu, qs, o);
        }
        float invk = 1.0f / fmaxf(sqrtf(ks), 1e-12f);
        float invq = s_qk / fmaxf(sqrtf(qs), 1e-12f);

        size_t off = ((size_t)(b*NHh + h)*Ll + l)*QKD;
#pragma unroll
        for (int g=0; g<3; g++) {
            int t = g*64 + 2*lane;
            *(__half2*)&g_k[off + t] = __floats2half2_rn(kv[2*g]*invk, kv[2*g+1]*invk);
            *(__half2*)&g_q[off + t] = __floats2half2_rn(qv[2*g]*invq, qv[2*g+1]*invq);
        }
        return;
    }

    // ---- vtrans region ----
    const int vb = bid - PREP_WBLK;
    const int bh = vb >> 5, lxb = vb & 31;
    const int b = bh >> 4, h = bh & 15;
    const int l0 = lxb * 64;

    for (int i = tid; i < 64*16; i += 256) {
        int l = i >> 4, ch = i & 15;
        *(uint4*)&tv[l][ch*8] =
            *(const uint4*)(g_c2 + ((size_t)(b*Ll + l0 + l))*N2 + Dd + h*DHh + ch*8);
    }
    __syncthreads();
    for (int i = tid; i < 128*8; i += 256) {
        int d = i >> 3, ch = i & 7;
        __half2 p[4];
#pragma unroll
        for (int u=0;u<4;u++) {
            int l = ch*8 + u*2;
            p[u] = __halves2half2(tv[l][d], tv[l+1][d]);
        }
        *(uint4*)(g_vt + (size_t)bh*DHh*Ll + (size_t)d*Ll + l0 + ch*8) = *(uint4*)p;
    }
}

// ---------------- fp16 flash attention (causal, BQ=256, BK=64) -------------
// Fixed-max softmax: scores <= s_qk (q,k unit-normalized, q scaled by s_qk),
// so exp uses constant C' = s_qk - 15*ln2 (2^15 bias keeps P in fp16 normal
// range; scale cancels between O and l_i). No running max, no O rescale.
#define QS 100
#define VS 36
#define KST (64*QS)
#define VST (128*VS)
#define BQA 256
__global__ void __launch_bounds__(512, 1) attn_h16(const float* __restrict__ s_qk_ptr)
{
    extern __shared__ unsigned smu[];
    const unsigned sQ = smem_u32(smu);          // [256][100]
    const unsigned sK = sQ + BQA*QS*4;          // 2 stages [64][100]
    const unsigned sV = sK + 2*KST*4;           // 2 stages [128][36]

    const int qt = (gridDim.x - 1) - blockIdx.x;
    const int bh = blockIdx.y;
    const int q0 = qt * BQA;
    const __half* Qg = g_q  + (size_t)bh*Ll*QKD + (size_t)q0*QKD;
    const __half* Kg = g_k  + (size_t)bh*Ll*QKD;
    const __half* Vg = g_vt + (size_t)bh*DHh*Ll;

    const float Cexp = *s_qk_ptr - 10.3972077084f;   // s_qk - 15*ln2

    const int tid  = threadIdx.x;
    const int lane = tid & 31;
    const int warp = tid >> 5;
    const int r = lane >> 2, c = lane & 3;
    const int ln15 = lane & 15;
    const int hi16 = (lane >> 4) * 16;
    const int m0 = warp * 16;

    auto fillKV = [&](int s, int k0) {
        const unsigned kS = sK + s*KST*4;
        const unsigned vS = sV + s*VST*4;
        for (int i = tid; i < 64*24; i += 512) {
            int row = i / 24, ch = i % 24;
            cp16(kS + (row*QS + ch*4)*4, Kg + (size_t)(k0+row)*QKD + ch*8);
        }
        for (int i = tid; i < 128*8; i += 512) {
            int d = i >> 3, ch = i & 7;
            cp16(vS + (d*VS + ch*4)*4, Vg + (size_t)d*Ll + k0 + ch*8);
        }
    };

    for (int i = tid; i < BQA*24; i += 512) {
        int row = i / 24, ch = i % 24;
        *(uint4*)&smu[row*QS + ch*4] = *(const uint4*)(Qg + (size_t)row*QKD + ch*8);
    }
    fillKV(0, 0);
    CP_COMMIT();

    const unsigned qbase = sQ + ((m0 + ln15)*QS)*4 + hi16;

    float O[16][4];
#pragma unroll
    for (int nb=0; nb<16; nb++)
#pragma unroll
        for (int t2=0; t2<4; t2++) O[nb][t2] = 0.f;
    float l_i[2] = {0.f, 0.f};

    const int nkt = 4*(qt+1);

    for (int kt = 0; kt < nkt; kt++) {
        CP_WAIT(0);
        __syncthreads();
        if (kt+1 < nkt) fillKV((kt+1)&1, (kt+1)*64);
        CP_COMMIT();

        const int k0 = kt*64;
        const bool active = (k0 <= q0 + m0 + 15);
        if (active) {
            const unsigned kS = sK + (kt&1)*KST*4;
            const unsigned vS = sV + (kt&1)*VST*4;

            float S[8][4];
#pragma unroll
            for (int j=0;j<8;j++)
#pragma unroll
                for (int t2=0;t2<4;t2++) S[j][t2]=0.f;

#pragma unroll
            for (int kk = 0; kk < 12; kk++) {
                unsigned a[4];
                ldsm4(a, qbase + kk*32);
#pragma unroll
                for (int p = 0; p < 4; p++) {
                    unsigned bq[4];
                    ldsm4(bq, kS + ((p*16 + ln15)*QS)*4 + hi16 + kk*32);
                    unsigned b0[2] = {bq[0], bq[2]};
                    unsigned b1[2] = {bq[1], bq[3]};
                    mma_h16(S[p*2  ], a, b0);
                    mma_h16(S[p*2+1], a, b1);
                }
            }

            if (k0 + 63 > q0 + m0) {
                const int row0 = q0 + m0 + r;
                const int row1 = row0 + 8;
#pragma unroll
                for (int j = 0; j < 8; j++) {
                    int col = k0 + j*8 + 2*c;
                    if (col   > row0) S[j][0] = -1e30f;
                    if (col+1 > row0) S[j][1] = -1e30f;
                    if (col   > row1) S[j][2] = -1e30f;
                    if (col+1 > row1) S[j][3] = -1e30f;
                }
            }

            // ---- fixed-max softmax: P = exp(S - Cexp), no rescale ----
            float rs0 = 0.f, rs1 = 0.f;
#pragma unroll
            for (int j=0;j<8;j++) {
                S[j][0] = __expf(S[j][0]-Cexp); rs0 += S[j][0];
                S[j][1] = __expf(S[j][1]-Cexp); rs0 += S[j][1];
                S[j][2] = __expf(S[j][2]-Cexp); rs1 += S[j][2];
                S[j][3] = __expf(S[j][3]-Cexp); rs1 += S[j][3];
            }
            rs0 += __shfl_xor_sync(0xffffffffu, rs0, 1);
            rs0 += __shfl_xor_sync(0xffffffffu, rs0, 2);
            rs1 += __shfl_xor_sync(0xffffffffu, rs1, 1);
            rs1 += __shfl_xor_sync(0xffffffffu, rs1, 2);
            l_i[0] += rs0;
            l_i[1] += rs1;

            // ---- P fragments directly from S accumulators ----
#pragma unroll
            for (int kk = 0; kk < 4; kk++) {
                unsigned pa[4];
                {
                    __half2 h0 = __floats2half2_rn(S[2*kk  ][0], S[2*kk  ][1]);
                    __half2 h1 = __floats2half2_rn(S[2*kk  ][2], S[2*kk  ][3]);
                    __half2 h2 = __floats2half2_rn(S[2*kk+1][0], S[2*kk+1][1]);
                    __half2 h3 = __floats2half2_rn(S[2*kk+1][2], S[2*kk+1][3]);
                    pa[0] = *(unsigned*)&h0;
                    pa[1] = *(unsigned*)&h1;
                    pa[2] = *(unsigned*)&h2;
                    pa[3] = *(unsigned*)&h3;
                }
#pragma unroll
                for (int p = 0; p < 8; p++) {
                    unsigned bq[4];
                    ldsm4(bq, vS + ((p*16 + ln15)*VS)*4 + hi16 + kk*32);
                    unsigned b0[2] = {bq[0], bq[2]};
                    unsigned b1[2] = {bq[1], bq[3]};
                    mma_h16(O[p*2  ], pa, b0);
                    mma_h16(O[p*2+1], pa, b1);
                }
            }
        }
    }

    const int b = bh >> 4, h = bh & 15;
    const float inv0 = 1.0f / l_i[0];
    const float inv1 = 1.0f / l_i[1];
    const int l0 = q0 + m0 + r;
    __half* d0 = g_ao + ((size_t)(b*Ll + l0    ))*Dd + h*DHh;
    __half* d1 = g_ao + ((size_t)(b*Ll + l0 + 8))*Dd + h*DHh;
#pragma unroll
    for (int nb=0; nb<16; nb++) {
        *(__half2*)&d0[nb*8 + 2*c] = __floats2half2_rn(O[nb][0]*inv0, O[nb][1]*inv0);
        *(__half2*)&d1[nb*8 + 2*c] = __floats2half2_rn(O[nb][2]*inv1, O[nb][3]*inv1);
    }
}

// ---------------- launch ----------------
extern "C" void kernel_launch(void* const* d_in, const int* in_sizes, int n_in,
                              void* d_out, int out_size)
{
    const float* x     = (const float*)d_in[0];
    const float* W_DKV = (const float*)d_in[1];
    const float* W_UK  = (const float*)d_in[2];
    const float* W_UV  = (const float*)d_in[3];
    const float* W_DQ  = (const float*)d_in[4];
    const float* W_UQ  = (const float*)d_in[5];
    const float* W_QR  = (const float*)d_in[6];
    const float* W_KR  = (const float*)d_in[7];
    const float* W_O   = (const float*)d_in[8];
    const float* s_qk  = (const float*)d_in[9];
    float* out = (float*)d_out;

    __half *xh, *w1t, *w2t, *w3t, *woT, *c1, *c2, *c3, *ao;
    cudaGetSymbolAddress((void**)&xh,  g_xh);
    cudaGetSymbolAddress((void**)&w1t, g_w1t);
    cudaGetSymbolAddress((void**)&w2t, g_w2t);
    cudaGetSymbolAddress((void**)&w3t, g_w3t);
    cudaGetSymbolAddress((void**)&woT, g_woT);
    cudaGetSymbolAddress((void**)&c1,  g_c1);
    cudaGetSymbolAddress((void**)&c2,  g_c2);
    cudaGetSymbolAddress((void**)&c3,  g_c3);
    cudaGetSymbolAddress((void**)&ao,  g_ao);

    const int gemm_smem = 6*GST*4;                              // 110592
    cudaFuncSetAttribute(h16_gemm<false>, cudaFuncAttributeMaxDynamicSharedMemorySize, gemm_smem);
    cudaFuncSetAttribute(h16_gemm<true>,  cudaFuncAttributeMaxDynamicSharedMemorySize, gemm_smem);
    cudaFuncSetAttribute(h16_gemm1x,      cudaFuncAttributeMaxDynamicSharedMemorySize, gemm_smem);
    cudaFuncSetAttribute(h16_gemm23,      cudaFuncAttributeMaxDynamicSharedMemorySize, gemm_smem);
    const int attn_smem = (BQA*QS + 2*KST + 2*VST) * 4;         // 190464
    cudaFuncSetAttribute(attn_h16, cudaFuncAttributeMaxDynamicSharedMemorySize, attn_smem);

    dim3 thr(256);

    // 1: pre (rope + cvt_x + w1t transposes)
    fused_pre<<<PRE_NBLK, thr>>>(x, W_DKV, W_DQ, W_KR);

    // 2: g1 fused with w2t/w3t/woT transposes
    h16_gemm1x<<<G1_NBLK, thr, gemm_smem>>>(xh, w1t, c1, W_UK, W_UV, W_UQ, W_QR, W_O);

    // 3: fused g2+g3
    h16_gemm23<<<dim3(N2/128 + N3/128, Mtok/128), thr, gemm_smem>>>(c1, w2t, w3t, c2, c3);

    // 4: prep + V transpose
    prep4<<<PREP_WBLK + 2048, thr>>>(s_qk);

    // 5: attention (fixed-max softmax)
    attn_h16<<<dim3(Ll/BQA, Bb*NHh), 512, attn_smem>>>(s_qk);

    // 6: output projection -> d_out
    h16_gemm<true><<<dim3(Dd/128, Mtok/128), thr, gemm_smem>>>(ao, woT, out, Dd, Dd, Dd, Dd);
}